// round 9
// baseline (speedup 1.0000x reference)
#include <cuda_runtime.h>
#include <cuda_bf16.h>
#include <cstdint>

// ---------------- problem constants ----------------
#define T_TOK   8192      // B*S
#define SEQ     2048
#define NBATCH  4
#define DIM     1024
#define NHEADS  16
#define HDIM    64
#define LATENT  128
#define QRANK   256

#define QSCALE  0.18033688011112042f   // (1/sqrt(64)) * log2(e)

// ---------------- scratch (device globals; no allocation) ----------------
__device__ float g_lat [T_TOK * LATENT];        // tf32 patterns
__device__ float g_k   [T_TOK * DIM];           // tf32 patterns, K natural [token][DIM]
__device__ uint32_t g_vt[(size_t)NBATCH * DIM * SEQ];  // tf32, V transposed [b][d][s]
__device__ float g_qc  [T_TOK * QRANK];         // tf32 patterns
__device__ float g_q   [T_TOK * DIM];           // tf32 patterns, pre-scaled by QSCALE
__device__ float g_ctx [T_TOK * DIM];           // tf32 patterns
__device__ uint32_t g_xt  [T_TOK * DIM];        // x as tf32
__device__ uint32_t g_wkvc[DIM * LATENT];       // transposed: [LATENT][DIM]
__device__ uint32_t g_wqc [DIM * QRANK];        // transposed: [QRANK][DIM]
__device__ uint32_t g_wkvu[LATENT * 2 * DIM];   // transposed: [2*DIM][LATENT]
__device__ uint32_t g_wqu [QRANK * DIM];        // transposed: [DIM][QRANK]
__device__ uint32_t g_wo  [DIM * DIM];          // transposed: [DIM][DIM]

// ---------------- helpers ----------------
__device__ __forceinline__ uint32_t f2t(float x) {
    uint32_t u;
    asm("cvt.rna.tf32.f32 %0, %1;" : "=r"(u) : "f"(x));
    return u;
}
__device__ __forceinline__ float ex2(float x) {
    float r;
    asm("ex2.approx.f32 %0, %1;" : "=f"(r) : "f"(x));
    return r;
}
__device__ __forceinline__ void mma8(float* c, const uint32_t* a, const uint32_t* b) {
    asm volatile(
        "mma.sync.aligned.m16n8k8.row.col.f32.tf32.tf32.f32 "
        "{%0,%1,%2,%3}, {%4,%5,%6,%7}, {%8,%9}, {%0,%1,%2,%3};"
        : "+f"(c[0]), "+f"(c[1]), "+f"(c[2]), "+f"(c[3])
        : "r"(a[0]), "r"(a[1]), "r"(a[2]), "r"(a[3]), "r"(b[0]), "r"(b[1]));
}
__device__ __forceinline__ void ldsm4(uint32_t* r, uint32_t saddr) {
    asm volatile("ldmatrix.sync.aligned.m8n8.x4.shared.b16 {%0,%1,%2,%3}, [%4];"
        : "=r"(r[0]), "=r"(r[1]), "=r"(r[2]), "=r"(r[3]) : "r"(saddr));
}
__device__ __forceinline__ void cpa16(uint32_t dst, const void* src) {
    asm volatile("cp.async.cg.shared.global [%0], [%1], 16;" :: "r"(dst), "l"(src));
}
__device__ __forceinline__ void cpa_commit() {
    asm volatile("cp.async.commit_group;");
}
template<int N>
__device__ __forceinline__ void cpa_wait() {
    asm volatile("cp.async.wait_group %0;" :: "n"(N));
}

// ---------------- converts ----------------
__global__ void cvt_x_kernel(const float4* __restrict__ src, uint4* __restrict__ dst, int n4)
{
    int i = blockIdx.x * 256 + threadIdx.x;
    if (i < n4) {
        float4 v = src[i];
        uint4 u;
        u.x = f2t(v.x); u.y = f2t(v.y); u.z = f2t(v.z); u.w = f2t(v.w);
        dst[i] = u;
    }
}

// transpose+convert all 5 weights in one launch: src [K][N] fp32 -> dst [N][K] tf32
__global__ __launch_bounds__(256)
void cvt_wT_kernel(
    const float* s0, uint32_t* d0, int K0, int N0, int t0,
    const float* s1, uint32_t* d1, int K1, int N1, int t1,
    const float* s2, uint32_t* d2, int K2, int N2, int t2,
    const float* s3, uint32_t* d3, int K3, int N3, int t3,
    const float* s4, uint32_t* d4, int K4, int N4)
{
    __shared__ uint32_t tb[32][33];
    int bx = blockIdx.x;
    const float* s; uint32_t* d; int K, N;
    if (bx < t0)              { s = s0; d = d0; K = K0; N = N0; }
    else if ((bx -= t0) < t1) { s = s1; d = d1; K = K1; N = N1; }
    else if ((bx -= t1) < t2) { s = s2; d = d2; K = K2; N = N2; }
    else if ((bx -= t2) < t3) { s = s3; d = d3; K = K3; N = N3; }
    else { bx -= t3;            s = s4; d = d4; K = K4; N = N4; }

    const int nx = N >> 5;
    const int k0 = (bx / nx) * 32, n0 = (bx % nx) * 32;
    const int tx = threadIdx.x & 31, ty = threadIdx.x >> 5;   // 32 x 8
#pragma unroll
    for (int dy = 0; dy < 32; dy += 8)
        tb[ty + dy][tx] = f2t(s[(size_t)(k0 + ty + dy) * N + n0 + tx]);
    __syncthreads();
#pragma unroll
    for (int dy = 0; dy < 32; dy += 8)
        d[(size_t)(n0 + ty + dy) * K + k0 + tx] = tb[tx][ty + dy];
}

// ---------------- GEMM body: C = A[M,K](tf32) @ Wt[N,K](tf32, transposed) + bias ----------------
// MODE 0: fp32 out. MODE 1: tf32-pattern out (scaled). MODE 2: kv_up split output:
//   cols < DIM -> K natural tf32 at C (stride DIM); cols >= DIM -> V transposed tf32 into g_vt.
#define A_STR 36
#define A_WORDS (128 * A_STR)             // 4608 words per operand per stage
#define STAGE_WORDS (2 * A_WORDS)
#define GEMM_SMEM (2 * STAGE_WORDS * 4)   // 73728 B

template<int MODE>
__device__ __forceinline__ void gemm_body(
    const uint32_t* __restrict__ A, const uint32_t* __restrict__ Wt,
    const float* __restrict__ bias, float* __restrict__ C,
    int N, int K, int m0, int n0, float scale, uint32_t* smg)
{
    const int tid  = threadIdx.x;
    const int lane = tid & 31;
    const int wid  = tid >> 5;
    const int wm   = (wid >> 2) * 64;
    const int wn   = (wid & 3) * 32;
    const int l4   = lane & 3;
    const int l2   = lane >> 2;

    const int ar0 = tid >> 3;
    const int ca  = (tid & 7) * 4;

    const int lrow = ((lane >> 3) & 1) * 8 + (lane & 7);
    const int lcol = (lane >> 4) * 4;
    const uint32_t smb = (uint32_t)__cvta_generic_to_shared(smg);

    float acc[4][4][4];
#pragma unroll
    for (int i = 0; i < 4; i++)
#pragma unroll
        for (int j = 0; j < 4; j++)
#pragma unroll
            for (int c = 0; c < 4; c++) acc[i][j][c] = 0.f;

    const int nk = K >> 5;

    auto issue = [&](int k0, int s) {
        uint32_t ab = smb + s * (STAGE_WORDS * 4);
        uint32_t bb = ab + A_WORDS * 4;
#pragma unroll
        for (int v = 0; v < 4; v++) {
            cpa16(ab + ((ar0 + v * 32) * A_STR + ca) * 4,
                  A  + (size_t)(m0 + ar0 + v * 32) * K + k0 + ca);
            cpa16(bb + ((ar0 + v * 32) * A_STR + ca) * 4,
                  Wt + (size_t)(n0 + ar0 + v * 32) * K + k0 + ca);
        }
        cpa_commit();
    };

    issue(0, 0);
    for (int kt = 0; kt < nk; kt++) {
        cpa_wait<0>();
        __syncthreads();
        if (kt + 1 < nk) issue((kt + 1) << 5, (kt + 1) & 1);

        const uint32_t asb = smb + (kt & 1) * (STAGE_WORDS * 4);
        const uint32_t bsb = asb + A_WORDS * 4;

#pragma unroll
        for (int kk = 0; kk < 4; kk++) {
            const int k = kk * 8;
            uint32_t af[4][4], br[2][4];
#pragma unroll
            for (int im = 0; im < 4; im++)
                ldsm4(af[im], asb + ((wm + im * 16 + lrow) * A_STR + k + lcol) * 4);
#pragma unroll
            for (int p = 0; p < 2; p++)
                ldsm4(br[p], bsb + ((wn + p * 16 + lrow) * A_STR + k + lcol) * 4);
            uint32_t bf[4][2] = {
                {br[0][0], br[0][2]}, {br[0][1], br[0][3]},
                {br[1][0], br[1][2]}, {br[1][1], br[1][3]}};
#pragma unroll
            for (int im = 0; im < 4; im++)
#pragma unroll
                for (int in = 0; in < 4; in++)
                    mma8(acc[im][in], af[im], bf[in]);
        }
    }

#pragma unroll
    for (int im = 0; im < 4; im++) {
        int row = m0 + wm + im * 16 + l2;
#pragma unroll
        for (int in = 0; in < 4; in++) {
            int col = n0 + wn + in * 8 + 2 * l4;
            float b0 = bias[col], b1 = bias[col + 1];
            if (MODE == 0) {
                *(float2*)&C[(size_t)row * N + col] =
                    make_float2(acc[im][in][0] + b0, acc[im][in][1] + b1);
                *(float2*)&C[(size_t)(row + 8) * N + col] =
                    make_float2(acc[im][in][2] + b0, acc[im][in][3] + b1);
            } else if (MODE == 1) {
                *(float2*)&C[(size_t)row * N + col] = make_float2(
                    __uint_as_float(f2t(scale * (acc[im][in][0] + b0))),
                    __uint_as_float(f2t(scale * (acc[im][in][1] + b1))));
                *(float2*)&C[(size_t)(row + 8) * N + col] = make_float2(
                    __uint_as_float(f2t(scale * (acc[im][in][2] + b0))),
                    __uint_as_float(f2t(scale * (acc[im][in][3] + b1))));
            } else {
                if (col < DIM) {   // K part: natural [token][DIM], tf32
                    *(float2*)&C[(size_t)row * DIM + col] = make_float2(
                        __uint_as_float(f2t(acc[im][in][0] + b0)),
                        __uint_as_float(f2t(acc[im][in][1] + b1)));
                    *(float2*)&C[(size_t)(row + 8) * DIM + col] = make_float2(
                        __uint_as_float(f2t(acc[im][in][2] + b0)),
                        __uint_as_float(f2t(acc[im][in][3] + b1)));
                } else {           // V part: transposed [b][d][s], tf32
                    int d  = col - DIM;
                    int bb = row >> 11;            // row / SEQ
                    int s  = row & (SEQ - 1);
                    uint32_t* v0 = g_vt + ((size_t)bb * DIM + d) * SEQ + s;
                    v0[0]           = f2t(acc[im][in][0] + b0);
                    v0[SEQ]         = f2t(acc[im][in][1] + b1);
                    v0[8]           = f2t(acc[im][in][2] + b0);
                    v0[SEQ + 8]     = f2t(acc[im][in][3] + b1);
                }
            }
        }
    }
}

template<int MODE>
__global__ __launch_bounds__(256, 2)
void gemm_tt_kernel(const uint32_t* __restrict__ A, const uint32_t* __restrict__ Wt,
                    const float* __restrict__ bias, float* __restrict__ C,
                    int N, int K, float scale)
{
    extern __shared__ uint32_t smg[];
    gemm_body<MODE>(A, Wt, bias, C, N, K, blockIdx.y * 128, blockIdx.x * 128, scale, smg);
}

// fused kv_latent (N=128) + q_c (N=256)
__global__ __launch_bounds__(256, 2)
void fused_latqc_kernel(const uint32_t* __restrict__ X,
                        const uint32_t* __restrict__ WkvcT, const float* __restrict__ bkvc, float* __restrict__ lat,
                        const uint32_t* __restrict__ WqcT,  const float* __restrict__ bqc,  float* __restrict__ qc)
{
    extern __shared__ uint32_t smg[];
    const int bx = blockIdx.x;
    if (bx == 0)
        gemm_body<1>(X, WkvcT, bkvc, lat, LATENT, DIM, blockIdx.y * 128, 0, 1.f, smg);
    else
        gemm_body<1>(X, WqcT, bqc, qc, QRANK, DIM, blockIdx.y * 128, (bx - 1) * 128, 1.f, smg);
}

// ---------------- causal flash attention, tf32, hd=64 ----------------
// BQ=128 q rows/CTA, 8 warps; kv tile 64, register-prefetch double buffer.
// Q/K natural + ldmatrix (proven); V transposed-in-gmem -> natural [d][kv] smem + ldmatrix;
// P permuted (proven).
#define BQ    128
#define QSTR  68    // mod 32 == 4 -> ldmatrix conflict-free
#define VSTR  68
#define PSTR  72
#define FL_SMEM ((BQ * QSTR + 64 * QSTR + 64 * VSTR + BQ * PSTR) * 4)  // 106496 B

__global__ __launch_bounds__(256, 2)
void flash_tf32_kernel(const uint32_t* __restrict__ Q, const uint32_t* __restrict__ Kp,
                       const uint32_t* __restrict__ Vt, float* __restrict__ Ctx)
{
    extern __shared__ uint32_t sm[];
    uint32_t* Qs = sm;                     // [BQ][QSTR] natural [q][d]
    uint32_t* Ks = Qs + BQ * QSTR;         // [64][QSTR] natural [kv][d]
    uint32_t* Vs = Ks + 64 * QSTR;         // [64][VSTR] natural [d][kv]
    uint32_t* Ps = Vs + 64 * VSTR;         // [BQ][PSTR] permuted

    const int qt = (gridDim.x - 1) - blockIdx.x;  // longest CTAs first
    const int h  = blockIdx.y;
    const int b  = blockIdx.z;
    const int q0 = qt * BQ;
    const int tid  = threadIdx.x;
    const int lane = tid & 31;
    const int w    = tid >> 5;
    const int l4   = lane & 3;
    const int l2   = lane >> 2;
    const int lrow0 = w * 16 + l2;
    const int lrow1 = lrow0 + 8;

    const int lrow = ((lane >> 3) & 1) * 8 + (lane & 7);
    const int lcol = (lane >> 4) * 4;
    const uint32_t qsb = (uint32_t)__cvta_generic_to_shared(Qs);
    const uint32_t ksb = (uint32_t)__cvta_generic_to_shared(Ks);
    const uint32_t vsb = (uint32_t)__cvta_generic_to_shared(Vs);

    const size_t qbase = ((size_t)(b * SEQ + q0)) * DIM + h * HDIM;
#pragma unroll
    for (int v = 0; v < 8; v++) {
        int i = tid + v * 256;
        int r = i >> 4, cv = i & 15;
        uint4 qv = *(const uint4*)(Q + qbase + (size_t)r * DIM + cv * 4);
        *(uint4*)(Qs + r * QSTR + cv * 4) = qv;
    }

    float mr0 = -1.0e30f, mr1 = -1.0e30f, lr0 = 0.f, lr1 = 0.f;
    float oacc[8][4];
#pragma unroll
    for (int n = 0; n < 8; n++)
#pragma unroll
        for (int c = 0; c < 4; c++) oacc[n][c] = 0.f;

    const int ntiles = 2 * qt + 2;
    uint4 kreg[4], vreg[4];

    auto gload = [&](int kt) {
        const size_t kb = ((size_t)(b * SEQ + kt * 64)) * DIM + h * HDIM;
        const size_t vb = ((size_t)(b * DIM + h * HDIM)) * SEQ + kt * 64;
#pragma unroll
        for (int v = 0; v < 4; v++) {
            int i = tid + v * 256;
            int r = i >> 4, cv = i & 15;
            kreg[v] = *(const uint4*)(Kp + kb + (size_t)r * DIM + cv * 4);
            vreg[v] = *(const uint4*)(Vt + vb + (size_t)r * SEQ + cv * 4);
        }
    };

    gload(0);

    for (int kt = 0; kt < ntiles; kt++) {
        __syncthreads();
#pragma unroll
        for (int v = 0; v < 4; v++) {
            int i = tid + v * 256;
            int r = i >> 4, cv = i & 15;
            *(uint4*)(Ks + r * QSTR + cv * 4) = kreg[v];
            *(uint4*)(Vs + r * VSTR + cv * 4) = vreg[v];
        }
        __syncthreads();

        if (kt + 1 < ntiles) gload(kt + 1);

        const int k0 = kt * 64;
        const bool active = (k0 <= q0 + w * 16 + 15);
        if (active) {
            // ---- S = Q K^T via ldmatrix ----
            float sacc[8][4];
#pragma unroll
            for (int n = 0; n < 8; n++)
#pragma unroll
                for (int c = 0; c < 4; c++) sacc[n][c] = 0.f;

#pragma unroll
            for (int kk = 0; kk < 8; kk++) {
                uint32_t a[4];
                ldsm4(a, qsb + ((w * 16 + lrow) * QSTR + kk * 8 + lcol) * 4);
#pragma unroll
                for (int p = 0; p < 4; p++) {
                    uint32_t kr[4];
                    ldsm4(kr, ksb + ((p * 16 + lrow) * QSTR + kk * 8 + lcol) * 4);
                    uint32_t b0[2] = {kr[0], kr[2]};
                    uint32_t b1[2] = {kr[1], kr[3]};
                    mma8(sacc[2 * p],     a, b0);
                    mma8(sacc[2 * p + 1], a, b1);
                }
            }

            // ---- causal mask ----
            if (k0 + 63 > q0 + w * 16) {
                const int g0 = q0 + lrow0, g1 = q0 + lrow1;
#pragma unroll
                for (int n = 0; n < 8; n++) {
                    int cg = k0 + n * 8 + 2 * l4;
                    if (cg     > g0) sacc[n][0] = -1.0e30f;
                    if (cg + 1 > g0) sacc[n][1] = -1.0e30f;
                    if (cg     > g1) sacc[n][2] = -1.0e30f;
                    if (cg + 1 > g1) sacc[n][3] = -1.0e30f;
                }
            }

            // ---- online softmax (log2 domain) ----
            float mx0 = -1.0e30f, mx1 = -1.0e30f;
#pragma unroll
            for (int n = 0; n < 8; n++) {
                mx0 = fmaxf(mx0, fmaxf(sacc[n][0], sacc[n][1]));
                mx1 = fmaxf(mx1, fmaxf(sacc[n][2], sacc[n][3]));
            }
            mx0 = fmaxf(mx0, __shfl_xor_sync(0xffffffffu, mx0, 1));
            mx0 = fmaxf(mx0, __shfl_xor_sync(0xffffffffu, mx0, 2));
            mx1 = fmaxf(mx1, __shfl_xor_sync(0xffffffffu, mx1, 1));
            mx1 = fmaxf(mx1, __shfl_xor_sync(0xffffffffu, mx1, 2));

            float mn0 = fmaxf(mr0, mx0), mn1 = fmaxf(mr1, mx1);
            float al0 = ex2(mr0 - mn0),  al1 = ex2(mr1 - mn1);
            float s0 = 0.f, s1 = 0.f;
#pragma unroll
            for (int n = 0; n < 8; n++) {
                float p0 = ex2(sacc[n][0] - mn0);
                float p1 = ex2(sacc[n][1] - mn0);
                float p2 = ex2(sacc[n][2] - mn1);
                float p3 = ex2(sacc[n][3] - mn1);
                sacc[n][0] = p0; sacc[n][1] = p1; sacc[n][2] = p2; sacc[n][3] = p3;
                s0 += p0 + p1;
                s1 += p2 + p3;
            }
            s0 += __shfl_xor_sync(0xffffffffu, s0, 1);
            s0 += __shfl_xor_sync(0xffffffffu, s0, 2);
            s1 += __shfl_xor_sync(0xffffffffu, s1, 1);
            s1 += __shfl_xor_sync(0xffffffffu, s1, 2);
            lr0 = lr0 * al0 + s0;
            lr1 = lr1 * al1 + s1;
            mr0 = mn0; mr1 = mn1;

#pragma unroll
            for (int n = 0; n < 8; n++) {
                oacc[n][0] *= al0; oacc[n][1] *= al0;
                oacc[n][2] *= al1; oacc[n][3] *= al1;
            }

            // ---- write P (permuted, warp-private rows) ----
            const int p0off = (l4 < 2) ? 4 * l4 : 4 * l4 - 7;
#pragma unroll
            for (int n = 0; n < 8; n++) {
                uint32_t* r0p = Ps + lrow0 * PSTR + n * 8 + p0off;
                uint32_t* r1p = Ps + lrow1 * PSTR + n * 8 + p0off;
                r0p[0] = f2t(sacc[n][0]); r0p[2] = f2t(sacc[n][1]);
                r1p[0] = f2t(sacc[n][2]); r1p[2] = f2t(sacc[n][3]);
            }
            __syncwarp();

            // ---- O += P @ V via ldmatrix on transposed V ----
#pragma unroll
            for (int kk = 0; kk < 8; kk++) {
                uint2 a01 = *(const uint2*)(Ps + lrow0 * PSTR + kk * 8 + 2 * l4);
                uint2 a23 = *(const uint2*)(Ps + lrow1 * PSTR + kk * 8 + 2 * l4);
                uint32_t a[4] = {a01.x, a23.x, a01.y, a23.y};
#pragma unroll
                for (int p = 0; p < 4; p++) {
                    uint32_t vr[4];
                    ldsm4(vr, vsb + ((p * 16 + lrow) * VSTR + kk * 8 + lcol) * 4);
                    uint32_t b0[2] = {vr[0], vr[2]};
                    uint32_t b1[2] = {vr[1], vr[3]};
                    mma8(oacc[2 * p],     a, b0);
                    mma8(oacc[2 * p + 1], a, b1);
                }
            }
            __syncwarp();
        }
    }

    const float inv0 = 1.f / lr0, inv1 = 1.f / lr1;
    const size_t ob0 = ((size_t)(b * SEQ + q0 + lrow0)) * DIM + h * HDIM;
    const size_t ob1 = ((size_t)(b * SEQ + q0 + lrow1)) * DIM + h * HDIM;
#pragma unroll
    for (int n = 0; n < 8; n++) {
        int col = n * 8 + 2 * l4;
        *(float2*)&Ctx[ob0 + col] = make_float2(__uint_as_float(f2t(oacc[n][0] * inv0)),
                                                __uint_as_float(f2t(oacc[n][1] * inv0)));
        *(float2*)&Ctx[ob1 + col] = make_float2(__uint_as_float(f2t(oacc[n][2] * inv1)),
                                                __uint_as_float(f2t(oacc[n][3] * inv1)));
    }
}

// ---------------- host launcher ----------------
extern "C" void kernel_launch(void* const* d_in, const int* in_sizes, int n_in,
                              void* d_out, int out_size)
{
    const float* x     = (const float*)d_in[0];
    // d_in[1] = mask (causal, hard-coded)
    const float* w_kvc = (const float*)d_in[2];
    const float* b_kvc = (const float*)d_in[3];
    const float* w_kvu = (const float*)d_in[4];
    const float* b_kvu = (const float*)d_in[5];
    const float* w_qc  = (const float*)d_in[6];
    const float* b_qc  = (const float*)d_in[7];
    const float* w_qu  = (const float*)d_in[8];
    const float* b_qu  = (const float*)d_in[9];
    const float* w_o   = (const float*)d_in[10];
    const float* b_o   = (const float*)d_in[11];
    float* out = (float*)d_out;

    float *lat, *kk, *qc, *q, *ctx;
    uint32_t *vt, *xt, *wkvc, *wqc, *wkvu, *wqu, *wo;
    cudaGetSymbolAddress((void**)&lat,  g_lat);
    cudaGetSymbolAddress((void**)&kk,   g_k);
    cudaGetSymbolAddress((void**)&vt,   g_vt);
    cudaGetSymbolAddress((void**)&qc,   g_qc);
    cudaGetSymbolAddress((void**)&q,    g_q);
    cudaGetSymbolAddress((void**)&ctx,  g_ctx);
    cudaGetSymbolAddress((void**)&xt,   g_xt);
    cudaGetSymbolAddress((void**)&wkvc, g_wkvc);
    cudaGetSymbolAddress((void**)&wqc,  g_wqc);
    cudaGetSymbolAddress((void**)&wkvu, g_wkvu);
    cudaGetSymbolAddress((void**)&wqu,  g_wqu);
    cudaGetSymbolAddress((void**)&wo,   g_wo);

    cudaFuncSetAttribute(gemm_tt_kernel<0>, cudaFuncAttributeMaxDynamicSharedMemorySize, GEMM_SMEM);
    cudaFuncSetAttribute(gemm_tt_kernel<1>, cudaFuncAttributeMaxDynamicSharedMemorySize, GEMM_SMEM);
    cudaFuncSetAttribute(gemm_tt_kernel<2>, cudaFuncAttributeMaxDynamicSharedMemorySize, GEMM_SMEM);
    cudaFuncSetAttribute(fused_latqc_kernel, cudaFuncAttributeMaxDynamicSharedMemorySize, GEMM_SMEM);
    cudaFuncSetAttribute(flash_tf32_kernel, cudaFuncAttributeMaxDynamicSharedMemorySize, FL_SMEM);

    // tile counts: (K/32)*(N/32)
    const int t0 = (DIM / 32) * (LATENT / 32);      // w_kvc  128
    const int t1 = (DIM / 32) * (QRANK / 32);       // w_qc   256
    const int t2 = (LATENT / 32) * (2 * DIM / 32);  // w_kvu  256
    const int t3 = (QRANK / 32) * (DIM / 32);       // w_qu   256
    const int t4 = (DIM / 32) * (DIM / 32);         // w_o   1024
    cvt_wT_kernel<<<t0 + t1 + t2 + t3 + t4, 256>>>(
        w_kvc, wkvc, DIM, LATENT, t0,
        w_qc,  wqc,  DIM, QRANK,  t1,
        w_kvu, wkvu, LATENT, 2 * DIM, t2,
        w_qu,  wqu,  QRANK, DIM, t3,
        w_o,   wo,   DIM, DIM);
    cvt_x_kernel<<<(T_TOK * DIM / 4 + 255) / 256, 256>>>((const float4*)x, (uint4*)xt, T_TOK * DIM / 4);

    // fused kv_latent [8192,128] + q_c [8192,256], tf32-out
    fused_latqc_kernel<<<dim3(3, T_TOK / 128), 256, GEMM_SMEM>>>(
        xt, wkvc, b_kvc, lat, wqc, b_qc, qc);
    // kv_up: K natural tf32 + V transposed tf32 (MODE 2)
    gemm_tt_kernel<2><<<dim3(2 * DIM / 128, T_TOK / 128), 256, GEMM_SMEM>>>(
        (const uint32_t*)lat, wkvu, b_kvu, kk, 2 * DIM, LATENT, 1.f);
    // Q = q_c @ w_qu + b  tf32-out * (log2e/8)
    gemm_tt_kernel<1><<<dim3(DIM / 128, T_TOK / 128), 256, GEMM_SMEM>>>(
        (const uint32_t*)qc, wqu, b_qu, q, DIM, QRANK, QSCALE);
    // causal flash attention -> ctx (tf32-out)
    flash_tf32_kernel<<<dim3(SEQ / BQ, NHEADS, NBATCH), 256, FL_SMEM>>>(
        (const uint32_t*)q, (const uint32_t*)kk, vt, ctx);
    // out = ctx @ w_o + b  fp32
    gemm_tt_kernel<0><<<dim3(DIM / 128, T_TOK / 128), 256, GEMM_SMEM>>>(
        (const uint32_t*)ctx, wo, b_o, out, DIM, DIM, 1.f);
}

// round 12
// speedup vs baseline: 1.0107x; 1.0107x over previous
#include <cuda_runtime.h>
#include <cuda_bf16.h>
#include <cstdint>

// ---------------- problem constants ----------------
#define T_TOK   8192      // B*S
#define SEQ     2048
#define NBATCH  4
#define DIM     1024
#define NHEADS  16
#define HDIM    64
#define LATENT  128
#define QRANK   256

#define QSCALE  0.18033688011112042f   // (1/sqrt(64)) * log2(e)

// ---------------- scratch (device globals; no allocation) ----------------
__device__ float g_lat [T_TOK * LATENT];        // tf32 patterns
__device__ float g_k   [T_TOK * DIM];           // tf32 patterns, K natural [token][DIM]
__device__ uint32_t g_vt[(size_t)NBATCH * DIM * SEQ];  // tf32, V transposed [b][d][s]
__device__ float g_qc  [T_TOK * QRANK];         // tf32 patterns
__device__ float g_q   [T_TOK * DIM];           // tf32 patterns, pre-scaled by QSCALE
__device__ float g_ctx [T_TOK * DIM];           // tf32 patterns
__device__ uint32_t g_xt  [T_TOK * DIM];        // x as tf32
__device__ uint32_t g_wkvc[DIM * LATENT];       // transposed: [LATENT][DIM]
__device__ uint32_t g_wqc [DIM * QRANK];        // transposed: [QRANK][DIM]
__device__ uint32_t g_wkvu[LATENT * 2 * DIM];   // transposed: [2*DIM][LATENT]
__device__ uint32_t g_wqu [QRANK * DIM];        // transposed: [DIM][QRANK]
__device__ uint32_t g_wo  [DIM * DIM];          // transposed: [DIM][DIM]

// ---------------- helpers ----------------
__device__ __forceinline__ uint32_t f2t(float x) {
    uint32_t u;
    asm("cvt.rna.tf32.f32 %0, %1;" : "=r"(u) : "f"(x));
    return u;
}
__device__ __forceinline__ float ex2(float x) {
    float r;
    asm("ex2.approx.f32 %0, %1;" : "=f"(r) : "f"(x));
    return r;
}
__device__ __forceinline__ void mma8(float* c, const uint32_t* a, const uint32_t* b) {
    asm volatile(
        "mma.sync.aligned.m16n8k8.row.col.f32.tf32.tf32.f32 "
        "{%0,%1,%2,%3}, {%4,%5,%6,%7}, {%8,%9}, {%0,%1,%2,%3};"
        : "+f"(c[0]), "+f"(c[1]), "+f"(c[2]), "+f"(c[3])
        : "r"(a[0]), "r"(a[1]), "r"(a[2]), "r"(a[3]), "r"(b[0]), "r"(b[1]));
}
__device__ __forceinline__ void ldsm4(uint32_t* r, uint32_t saddr) {
    asm volatile("ldmatrix.sync.aligned.m8n8.x4.shared.b16 {%0,%1,%2,%3}, [%4];"
        : "=r"(r[0]), "=r"(r[1]), "=r"(r[2]), "=r"(r[3]) : "r"(saddr));
}
__device__ __forceinline__ void cpa16(uint32_t dst, const void* src) {
    asm volatile("cp.async.cg.shared.global [%0], [%1], 16;" :: "r"(dst), "l"(src));
}
__device__ __forceinline__ void cpa_commit() {
    asm volatile("cp.async.commit_group;");
}
template<int N>
__device__ __forceinline__ void cpa_wait() {
    asm volatile("cp.async.wait_group %0;" :: "n"(N));
}

// ---------------- converts ----------------
__global__ void cvt_x_kernel(const float4* __restrict__ src, uint4* __restrict__ dst, int n4)
{
    int i = blockIdx.x * 256 + threadIdx.x;
    if (i < n4) {
        float4 v = src[i];
        uint4 u;
        u.x = f2t(v.x); u.y = f2t(v.y); u.z = f2t(v.z); u.w = f2t(v.w);
        dst[i] = u;
    }
}

// transpose+convert all 5 weights in one launch: src [K][N] fp32 -> dst [N][K] tf32
__global__ __launch_bounds__(256)
void cvt_wT_kernel(
    const float* s0, uint32_t* d0, int K0, int N0, int t0,
    const float* s1, uint32_t* d1, int K1, int N1, int t1,
    const float* s2, uint32_t* d2, int K2, int N2, int t2,
    const float* s3, uint32_t* d3, int K3, int N3, int t3,
    const float* s4, uint32_t* d4, int K4, int N4)
{
    __shared__ uint32_t tb[32][33];
    int bx = blockIdx.x;
    const float* s; uint32_t* d; int K, N;
    if (bx < t0)              { s = s0; d = d0; K = K0; N = N0; }
    else if ((bx -= t0) < t1) { s = s1; d = d1; K = K1; N = N1; }
    else if ((bx -= t1) < t2) { s = s2; d = d2; K = K2; N = N2; }
    else if ((bx -= t2) < t3) { s = s3; d = d3; K = K3; N = N3; }
    else { bx -= t3;            s = s4; d = d4; K = K4; N = N4; }

    const int nx = N >> 5;
    const int k0 = (bx / nx) * 32, n0 = (bx % nx) * 32;
    const int tx = threadIdx.x & 31, ty = threadIdx.x >> 5;   // 32 x 8
#pragma unroll
    for (int dy = 0; dy < 32; dy += 8)
        tb[ty + dy][tx] = f2t(s[(size_t)(k0 + ty + dy) * N + n0 + tx]);
    __syncthreads();
#pragma unroll
    for (int dy = 0; dy < 32; dy += 8)
        d[(size_t)(n0 + ty + dy) * K + k0 + tx] = tb[tx][ty + dy];
}

// ---------------- mma.sync GEMM: C = A[M,K](tf32) @ Wt[N,K]^T + bias ----------------
// Block tile 128x64, BK=32, 256 threads = 8 warps (4m x 2n), warp tile 32x32.
// 2-stage cp.async, single barrier per k-tile, ldmatrix fragments.
// acc = 32 regs/thread -> __launch_bounds__(256,3): 3 CTAs/SM, 24 warps/SM.
// MODE 0: fp32 out. MODE 1: tf32 pattern of scale*(acc+bias). MODE 2: kv_up K/V split.
#define A_STR 36
#define A_WORDS (128 * A_STR)             // 4608
#define B_WORDS (64 * A_STR)              // 2304
#define STAGE_WORDS (A_WORDS + B_WORDS)   // 6912
#define GEMM_SMEM (2 * STAGE_WORDS * 4)   // 55296 B

template<int MODE>
__device__ __forceinline__ void gemm_body(
    const uint32_t* __restrict__ A, const uint32_t* __restrict__ Wt,
    const float* __restrict__ bias, float* __restrict__ C,
    int N, int K, int m0, int n0, float scale, uint32_t* smg)
{
    const int tid  = threadIdx.x;
    const int lane = tid & 31;
    const int wid  = tid >> 5;
    const int wm   = (wid >> 1) * 32;   // warp m offset (4 warps down)
    const int wn   = (wid & 1) * 32;    // warp n offset (2 warps across)
    const int l4   = lane & 3;
    const int l2   = lane >> 2;

    const int ar0 = tid >> 3;          // staging row base (+32 per v)
    const int ca  = (tid & 7) * 4;     // staging col base

    const int lrow = ((lane >> 3) & 1) * 8 + (lane & 7);
    const int lcol = (lane >> 4) * 4;
    const uint32_t smb = (uint32_t)__cvta_generic_to_shared(smg);

    float acc[2][4][4];
#pragma unroll
    for (int i = 0; i < 2; i++)
#pragma unroll
        for (int j = 0; j < 4; j++)
#pragma unroll
            for (int c = 0; c < 4; c++) acc[i][j][c] = 0.f;

    const int nk = K >> 5;

    auto issue = [&](int k0, int s) {
        uint32_t ab = smb + s * (STAGE_WORDS * 4);
        uint32_t bb = ab + A_WORDS * 4;
#pragma unroll
        for (int v = 0; v < 4; v++)
            cpa16(ab + ((ar0 + v * 32) * A_STR + ca) * 4,
                  A + (size_t)(m0 + ar0 + v * 32) * K + k0 + ca);
#pragma unroll
        for (int v = 0; v < 2; v++)
            cpa16(bb + ((ar0 + v * 32) * A_STR + ca) * 4,
                  Wt + (size_t)(n0 + ar0 + v * 32) * K + k0 + ca);
        cpa_commit();
    };

    issue(0, 0);
    for (int kt = 0; kt < nk; kt++) {
        cpa_wait<0>();
        __syncthreads();
        if (kt + 1 < nk) issue((kt + 1) << 5, (kt + 1) & 1);

        const uint32_t asb = smb + (kt & 1) * (STAGE_WORDS * 4);
        const uint32_t bsb = asb + A_WORDS * 4;

#pragma unroll
        for (int kk = 0; kk < 4; kk++) {
            const int k = kk * 8;
            uint32_t af[2][4], br[2][4];
#pragma unroll
            for (int im = 0; im < 2; im++)
                ldsm4(af[im], asb + ((wm + im * 16 + lrow) * A_STR + k + lcol) * 4);
#pragma unroll
            for (int p = 0; p < 2; p++)
                ldsm4(br[p], bsb + ((wn + p * 16 + lrow) * A_STR + k + lcol) * 4);
            uint32_t bf[4][2] = {
                {br[0][0], br[0][2]}, {br[0][1], br[0][3]},
                {br[1][0], br[1][2]}, {br[1][1], br[1][3]}};
#pragma unroll
            for (int im = 0; im < 2; im++)
#pragma unroll
                for (int in = 0; in < 4; in++)
                    mma8(acc[im][in], af[im], bf[in]);
        }
    }

#pragma unroll
    for (int im = 0; im < 2; im++) {
        int row = m0 + wm + im * 16 + l2;
#pragma unroll
        for (int in = 0; in < 4; in++) {
            int col = n0 + wn + in * 8 + 2 * l4;
            float b0 = bias[col], b1 = bias[col + 1];
            if (MODE == 0) {
                *(float2*)&C[(size_t)row * N + col] =
                    make_float2(acc[im][in][0] + b0, acc[im][in][1] + b1);
                *(float2*)&C[(size_t)(row + 8) * N + col] =
                    make_float2(acc[im][in][2] + b0, acc[im][in][3] + b1);
            } else if (MODE == 1) {
                *(float2*)&C[(size_t)row * N + col] = make_float2(
                    __uint_as_float(f2t(scale * (acc[im][in][0] + b0))),
                    __uint_as_float(f2t(scale * (acc[im][in][1] + b1))));
                *(float2*)&C[(size_t)(row + 8) * N + col] = make_float2(
                    __uint_as_float(f2t(scale * (acc[im][in][2] + b0))),
                    __uint_as_float(f2t(scale * (acc[im][in][3] + b1))));
            } else {   // MODE 2: kv_up split output
                if (col < DIM) {   // K part: natural [token][DIM], tf32
                    *(float2*)&C[(size_t)row * DIM + col] = make_float2(
                        __uint_as_float(f2t(acc[im][in][0] + b0)),
                        __uint_as_float(f2t(acc[im][in][1] + b1)));
                    *(float2*)&C[(size_t)(row + 8) * DIM + col] = make_float2(
                        __uint_as_float(f2t(acc[im][in][2] + b0)),
                        __uint_as_float(f2t(acc[im][in][3] + b1)));
                } else {           // V part: transposed [b][d][s], tf32
                    int d  = col - DIM;
                    int bb = row >> 11;            // row / SEQ
                    int s  = row & (SEQ - 1);
                    uint32_t* v0 = g_vt + ((size_t)bb * DIM + d) * SEQ + s;
                    v0[0]       = f2t(acc[im][in][0] + b0);
                    v0[SEQ]     = f2t(acc[im][in][1] + b1);
                    v0[8]       = f2t(acc[im][in][2] + b0);
                    v0[SEQ + 8] = f2t(acc[im][in][3] + b1);
                }
            }
        }
    }
}

template<int MODE>
__global__ __launch_bounds__(256, 3)
void gemm_tt_kernel(const uint32_t* __restrict__ A, const uint32_t* __restrict__ Wt,
                    const float* __restrict__ bias, float* __restrict__ C,
                    int N, int K, float scale)
{
    extern __shared__ uint32_t smg[];
    gemm_body<MODE>(A, Wt, bias, C, N, K, blockIdx.y * 128, blockIdx.x * 64, scale, smg);
}

// fused kv_latent (N=128 -> 2 n-tiles) + q_c (N=256 -> 4 n-tiles): grid.x = 6
__global__ __launch_bounds__(256, 3)
void fused_latqc_kernel(const uint32_t* __restrict__ X,
                        const uint32_t* __restrict__ WkvcT, const float* __restrict__ bkvc, float* __restrict__ lat,
                        const uint32_t* __restrict__ WqcT,  const float* __restrict__ bqc,  float* __restrict__ qc)
{
    extern __shared__ uint32_t smg[];
    const int bx = blockIdx.x;
    if (bx < 2)
        gemm_body<1>(X, WkvcT, bkvc, lat, LATENT, DIM, blockIdx.y * 128, bx * 64, 1.f, smg);
    else
        gemm_body<1>(X, WqcT, bqc, qc, QRANK, DIM, blockIdx.y * 128, (bx - 2) * 64, 1.f, smg);
}

// fused kv_up (N=2048, K=128 -> 32 n-tiles, MODE2) + q_up (N=1024, K=256 -> 16 n-tiles, MODE1)
__global__ __launch_bounds__(256, 3)
void fused_kvq_kernel(const uint32_t* __restrict__ Lat, const uint32_t* __restrict__ WkvuT,
                      const float* __restrict__ bkvu, float* __restrict__ Kout,
                      const uint32_t* __restrict__ Qc, const uint32_t* __restrict__ WquT,
                      const float* __restrict__ bqu, float* __restrict__ Qout)
{
    extern __shared__ uint32_t smg[];
    const int bx = blockIdx.x;
    if (bx < 32)
        gemm_body<2>(Lat, WkvuT, bkvu, Kout, 2 * DIM, LATENT, blockIdx.y * 128, bx * 64, 1.f, smg);
    else
        gemm_body<1>(Qc, WquT, bqu, Qout, DIM, QRANK, blockIdx.y * 128, (bx - 32) * 64, QSCALE, smg);
}

// ---------------- causal flash attention, tf32, hd=64 (round-9 proven, unchanged) ----------------
#define BQ    128
#define QSTR  68
#define VSTR  68
#define PSTR  72
#define FL_SMEM ((BQ * QSTR + 64 * QSTR + 64 * VSTR + BQ * PSTR) * 4)  // 106496 B

__global__ __launch_bounds__(256, 2)
void flash_tf32_kernel(const uint32_t* __restrict__ Q, const uint32_t* __restrict__ Kp,
                       const uint32_t* __restrict__ Vt, float* __restrict__ Ctx)
{
    extern __shared__ uint32_t sm[];
    uint32_t* Qs = sm;
    uint32_t* Ks = Qs + BQ * QSTR;
    uint32_t* Vs = Ks + 64 * QSTR;
    uint32_t* Ps = Vs + 64 * VSTR;

    const int qt = (gridDim.x - 1) - blockIdx.x;
    const int h  = blockIdx.y;
    const int b  = blockIdx.z;
    const int q0 = qt * BQ;
    const int tid  = threadIdx.x;
    const int lane = tid & 31;
    const int w    = tid >> 5;
    const int l4   = lane & 3;
    const int l2   = lane >> 2;
    const int lrow0 = w * 16 + l2;
    const int lrow1 = lrow0 + 8;

    const int lrow = ((lane >> 3) & 1) * 8 + (lane & 7);
    const int lcol = (lane >> 4) * 4;
    const uint32_t qsb = (uint32_t)__cvta_generic_to_shared(Qs);
    const uint32_t ksb = (uint32_t)__cvta_generic_to_shared(Ks);
    const uint32_t vsb = (uint32_t)__cvta_generic_to_shared(Vs);

    const size_t qbase = ((size_t)(b * SEQ + q0)) * DIM + h * HDIM;
#pragma unroll
    for (int v = 0; v < 8; v++) {
        int i = tid + v * 256;
        int r = i >> 4, cv = i & 15;
        uint4 qv = *(const uint4*)(Q + qbase + (size_t)r * DIM + cv * 4);
        *(uint4*)(Qs + r * QSTR + cv * 4) = qv;
    }

    float mr0 = -1.0e30f, mr1 = -1.0e30f, lr0 = 0.f, lr1 = 0.f;
    float oacc[8][4];
#pragma unroll
    for (int n = 0; n < 8; n++)
#pragma unroll
        for (int c = 0; c < 4; c++) oacc[n][c] = 0.f;

    const int ntiles = 2 * qt + 2;
    uint4 kreg[4], vreg[4];

    auto gload = [&](int kt) {
        const size_t kb = ((size_t)(b * SEQ + kt * 64)) * DIM + h * HDIM;
        const size_t vb = ((size_t)(b * DIM + h * HDIM)) * SEQ + kt * 64;
#pragma unroll
        for (int v = 0; v < 4; v++) {
            int i = tid + v * 256;
            int r = i >> 4, cv = i & 15;
            kreg[v] = *(const uint4*)(Kp + kb + (size_t)r * DIM + cv * 4);
            vreg[v] = *(const uint4*)(Vt + vb + (size_t)r * SEQ + cv * 4);
        }
    };

    gload(0);

    for (int kt = 0; kt < ntiles; kt++) {
        __syncthreads();
#pragma unroll
        for (int v = 0; v < 4; v++) {
            int i = tid + v * 256;
            int r = i >> 4, cv = i & 15;
            *(uint4*)(Ks + r * QSTR + cv * 4) = kreg[v];
            *(uint4*)(Vs + r * VSTR + cv * 4) = vreg[v];
        }
        __syncthreads();

        if (kt + 1 < ntiles) gload(kt + 1);

        const int k0 = kt * 64;
        const bool active = (k0 <= q0 + w * 16 + 15);
        if (active) {
            float sacc[8][4];
#pragma unroll
            for (int n = 0; n < 8; n++)
#pragma unroll
                for (int c = 0; c < 4; c++) sacc[n][c] = 0.f;

#pragma unroll
            for (int kk = 0; kk < 8; kk++) {
                uint32_t a[4];
                ldsm4(a, qsb + ((w * 16 + lrow) * QSTR + kk * 8 + lcol) * 4);
#pragma unroll
                for (int p = 0; p < 4; p++) {
                    uint32_t kr[4];
                    ldsm4(kr, ksb + ((p * 16 + lrow) * QSTR + kk * 8 + lcol) * 4);
                    uint32_t b0[2] = {kr[0], kr[2]};
                    uint32_t b1[2] = {kr[1], kr[3]};
                    mma8(sacc[2 * p],     a, b0);
                    mma8(sacc[2 * p + 1], a, b1);
                }
            }

            if (k0 + 63 > q0 + w * 16) {
                const int g0 = q0 + lrow0, g1 = q0 + lrow1;
#pragma unroll
                for (int n = 0; n < 8; n++) {
                    int cg = k0 + n * 8 + 2 * l4;
                    if (cg     > g0) sacc[n][0] = -1.0e30f;
                    if (cg + 1 > g0) sacc[n][1] = -1.0e30f;
                    if (cg     > g1) sacc[n][2] = -1.0e30f;
                    if (cg + 1 > g1) sacc[n][3] = -1.0e30f;
                }
            }

            float mx0 = -1.0e30f, mx1 = -1.0e30f;
#pragma unroll
            for (int n = 0; n < 8; n++) {
                mx0 = fmaxf(mx0, fmaxf(sacc[n][0], sacc[n][1]));
                mx1 = fmaxf(mx1, fmaxf(sacc[n][2], sacc[n][3]));
            }
            mx0 = fmaxf(mx0, __shfl_xor_sync(0xffffffffu, mx0, 1));
            mx0 = fmaxf(mx0, __shfl_xor_sync(0xffffffffu, mx0, 2));
            mx1 = fmaxf(mx1, __shfl_xor_sync(0xffffffffu, mx1, 1));
            mx1 = fmaxf(mx1, __shfl_xor_sync(0xffffffffu, mx1, 2));

            float mn0 = fmaxf(mr0, mx0), mn1 = fmaxf(mr1, mx1);
            float al0 = ex2(mr0 - mn0),  al1 = ex2(mr1 - mn1);
            float s0 = 0.f, s1 = 0.f;
#pragma unroll
            for (int n = 0; n < 8; n++) {
                float p0 = ex2(sacc[n][0] - mn0);
                float p1 = ex2(sacc[n][1] - mn0);
                float p2 = ex2(sacc[n][2] - mn1);
                float p3 = ex2(sacc[n][3] - mn1);
                sacc[n][0] = p0; sacc[n][1] = p1; sacc[n][2] = p2; sacc[n][3] = p3;
                s0 += p0 + p1;
                s1 += p2 + p3;
            }
            s0 += __shfl_xor_sync(0xffffffffu, s0, 1);
            s0 += __shfl_xor_sync(0xffffffffu, s0, 2);
            s1 += __shfl_xor_sync(0xffffffffu, s1, 1);
            s1 += __shfl_xor_sync(0xffffffffu, s1, 2);
            lr0 = lr0 * al0 + s0;
            lr1 = lr1 * al1 + s1;
            mr0 = mn0; mr1 = mn1;

#pragma unroll
            for (int n = 0; n < 8; n++) {
                oacc[n][0] *= al0; oacc[n][1] *= al0;
                oacc[n][2] *= al1; oacc[n][3] *= al1;
            }

            const int p0off = (l4 < 2) ? 4 * l4 : 4 * l4 - 7;
#pragma unroll
            for (int n = 0; n < 8; n++) {
                uint32_t* r0p = Ps + lrow0 * PSTR + n * 8 + p0off;
                uint32_t* r1p = Ps + lrow1 * PSTR + n * 8 + p0off;
                r0p[0] = f2t(sacc[n][0]); r0p[2] = f2t(sacc[n][1]);
                r1p[0] = f2t(sacc[n][2]); r1p[2] = f2t(sacc[n][3]);
            }
            __syncwarp();

#pragma unroll
            for (int kk = 0; kk < 8; kk++) {
                uint2 a01 = *(const uint2*)(Ps + lrow0 * PSTR + kk * 8 + 2 * l4);
                uint2 a23 = *(const uint2*)(Ps + lrow1 * PSTR + kk * 8 + 2 * l4);
                uint32_t a[4] = {a01.x, a23.x, a01.y, a23.y};
#pragma unroll
                for (int p = 0; p < 4; p++) {
                    uint32_t vr[4];
                    ldsm4(vr, vsb + ((p * 16 + lrow) * VSTR + kk * 8 + lcol) * 4);
                    uint32_t b0[2] = {vr[0], vr[2]};
                    uint32_t b1[2] = {vr[1], vr[3]};
                    mma8(oacc[2 * p],     a, b0);
                    mma8(oacc[2 * p + 1], a, b1);
                }
            }
            __syncwarp();
        }
    }

    const float inv0 = 1.f / lr0, inv1 = 1.f / lr1;
    const size_t ob0 = ((size_t)(b * SEQ + q0 + lrow0)) * DIM + h * HDIM;
    const size_t ob1 = ((size_t)(b * SEQ + q0 + lrow1)) * DIM + h * HDIM;
#pragma unroll
    for (int n = 0; n < 8; n++) {
        int col = n * 8 + 2 * l4;
        *(float2*)&Ctx[ob0 + col] = make_float2(__uint_as_float(f2t(oacc[n][0] * inv0)),
                                                __uint_as_float(f2t(oacc[n][1] * inv0)));
        *(float2*)&Ctx[ob1 + col] = make_float2(__uint_as_float(f2t(oacc[n][2] * inv1)),
                                                __uint_as_float(f2t(oacc[n][3] * inv1)));
    }
}

// ---------------- host launcher ----------------
extern "C" void kernel_launch(void* const* d_in, const int* in_sizes, int n_in,
                              void* d_out, int out_size)
{
    const float* x     = (const float*)d_in[0];
    // d_in[1] = mask (causal, hard-coded)
    const float* w_kvc = (const float*)d_in[2];
    const float* b_kvc = (const float*)d_in[3];
    const float* w_kvu = (const float*)d_in[4];
    const float* b_kvu = (const float*)d_in[5];
    const float* w_qc  = (const float*)d_in[6];
    const float* b_qc  = (const float*)d_in[7];
    const float* w_qu  = (const float*)d_in[8];
    const float* b_qu  = (const float*)d_in[9];
    const float* w_o   = (const float*)d_in[10];
    const float* b_o   = (const float*)d_in[11];
    float* out = (float*)d_out;

    float *lat, *kk, *qc, *q, *ctx;
    uint32_t *vt, *xt, *wkvc, *wqc, *wkvu, *wqu, *wo;
    cudaGetSymbolAddress((void**)&lat,  g_lat);
    cudaGetSymbolAddress((void**)&kk,   g_k);
    cudaGetSymbolAddress((void**)&vt,   g_vt);
    cudaGetSymbolAddress((void**)&qc,   g_qc);
    cudaGetSymbolAddress((void**)&q,    g_q);
    cudaGetSymbolAddress((void**)&ctx,  g_ctx);
    cudaGetSymbolAddress((void**)&xt,   g_xt);
    cudaGetSymbolAddress((void**)&wkvc, g_wkvc);
    cudaGetSymbolAddress((void**)&wqc,  g_wqc);
    cudaGetSymbolAddress((void**)&wkvu, g_wkvu);
    cudaGetSymbolAddress((void**)&wqu,  g_wqu);
    cudaGetSymbolAddress((void**)&wo,   g_wo);

    cudaFuncSetAttribute(gemm_tt_kernel<0>, cudaFuncAttributeMaxDynamicSharedMemorySize, GEMM_SMEM);
    cudaFuncSetAttribute(fused_latqc_kernel, cudaFuncAttributeMaxDynamicSharedMemorySize, GEMM_SMEM);
    cudaFuncSetAttribute(fused_kvq_kernel, cudaFuncAttributeMaxDynamicSharedMemorySize, GEMM_SMEM);
    cudaFuncSetAttribute(flash_tf32_kernel, cudaFuncAttributeMaxDynamicSharedMemorySize, FL_SMEM);

    const int t0 = (DIM / 32) * (LATENT / 32);
    const int t1 = (DIM / 32) * (QRANK / 32);
    const int t2 = (LATENT / 32) * (2 * DIM / 32);
    const int t3 = (QRANK / 32) * (DIM / 32);
    const int t4 = (DIM / 32) * (DIM / 32);
    cvt_wT_kernel<<<t0 + t1 + t2 + t3 + t4, 256>>>(
        w_kvc, wkvc, DIM, LATENT, t0,
        w_qc,  wqc,  DIM, QRANK,  t1,
        w_kvu, wkvu, LATENT, 2 * DIM, t2,
        w_qu,  wqu,  QRANK, DIM, t3,
        w_o,   wo,   DIM, DIM);
    cvt_x_kernel<<<(T_TOK * DIM / 4 + 255) / 256, 256>>>((const float4*)x, (uint4*)xt, T_TOK * DIM / 4);

    // fused kv_latent + q_c  (6 x 64 CTAs, K=1024)
    fused_latqc_kernel<<<dim3(6, T_TOK / 128), 256, GEMM_SMEM>>>(
        xt, wkvc, b_kvc, lat, wqc, b_qc, qc);
    // fused kv_up (MODE2, K/V split) + q_up (MODE1)  (48 x 64 CTAs)
    fused_kvq_kernel<<<dim3(48, T_TOK / 128), 256, GEMM_SMEM>>>(
        (const uint32_t*)lat, wkvu, b_kvu, kk,
        (const uint32_t*)qc, wqu, b_qu, q);
    // causal flash attention -> ctx (tf32-out)
    flash_tf32_kernel<<<dim3(SEQ / BQ, NHEADS, NBATCH), 256, FL_SMEM>>>(
        (const uint32_t*)q, (const uint32_t*)kk, vt, ctx);
    // out = ctx @ w_o + b  (16 x 64 CTAs, fp32 out)
    gemm_tt_kernel<0><<<dim3(DIM / 64, T_TOK / 128), 256, GEMM_SMEM>>>(
        (const uint32_t*)ctx, wo, b_o, out, DIM, DIM, 1.f);
}

// round 13
// speedup vs baseline: 1.1671x; 1.1548x over previous
#include <cuda_runtime.h>
#include <cuda_bf16.h>
#include <cstdint>

// ---------------- problem constants ----------------
#define T_TOK   8192      // B*S
#define SEQ     2048
#define NBATCH  4
#define DIM     1024
#define NHEADS  16
#define HDIM    64
#define LATENT  128
#define QRANK   256

#define QSCALE  0.18033688011112042f   // (1/sqrt(64)) * log2(e)

// ---------------- scratch (device globals; no allocation) ----------------
__device__ float g_lat [T_TOK * LATENT];        // tf32 patterns
__device__ uint16_t g_kb[T_TOK * DIM];          // K as bf16, natural [token][DIM]
__device__ uint32_t g_vt[(size_t)NBATCH * DIM * SEQ];  // tf32, V transposed [b][d][s]
__device__ float g_qc  [T_TOK * QRANK];         // tf32 patterns
__device__ uint16_t g_qb[T_TOK * DIM];          // Q as bf16, pre-scaled by QSCALE
__device__ float g_ctx [T_TOK * DIM];           // tf32 patterns
__device__ uint32_t g_xt  [T_TOK * DIM];        // x as tf32
__device__ uint32_t g_wkvc[DIM * LATENT];       // transposed: [LATENT][DIM]
__device__ uint32_t g_wqc [DIM * QRANK];        // transposed: [QRANK][DIM]
__device__ uint32_t g_wkvu[LATENT * 2 * DIM];   // transposed: [2*DIM][LATENT]
__device__ uint32_t g_wqu [QRANK * DIM];        // transposed: [DIM][QRANK]
__device__ uint32_t g_wo  [DIM * DIM];          // transposed: [DIM][DIM]

// ---------------- helpers ----------------
__device__ __forceinline__ uint32_t f2t(float x) {
    uint32_t u;
    asm("cvt.rna.tf32.f32 %0, %1;" : "=r"(u) : "f"(x));
    return u;
}
__device__ __forceinline__ uint32_t bf2(float lo, float hi) {   // pack {lo, hi} as bf16x2
    uint32_t r;
    asm("cvt.rn.bf16x2.f32 %0, %1, %2;" : "=r"(r) : "f"(hi), "f"(lo));
    return r;
}
__device__ __forceinline__ float ex2(float x) {
    float r;
    asm("ex2.approx.f32 %0, %1;" : "=f"(r) : "f"(x));
    return r;
}
__device__ __forceinline__ void mma8(float* c, const uint32_t* a, const uint32_t* b) {
    asm volatile(
        "mma.sync.aligned.m16n8k8.row.col.f32.tf32.tf32.f32 "
        "{%0,%1,%2,%3}, {%4,%5,%6,%7}, {%8,%9}, {%0,%1,%2,%3};"
        : "+f"(c[0]), "+f"(c[1]), "+f"(c[2]), "+f"(c[3])
        : "r"(a[0]), "r"(a[1]), "r"(a[2]), "r"(a[3]), "r"(b[0]), "r"(b[1]));
}
__device__ __forceinline__ void mma16(float* c, const uint32_t* a, uint32_t b0, uint32_t b1) {
    asm volatile(
        "mma.sync.aligned.m16n8k16.row.col.f32.bf16.bf16.f32 "
        "{%0,%1,%2,%3}, {%4,%5,%6,%7}, {%8,%9}, {%0,%1,%2,%3};"
        : "+f"(c[0]), "+f"(c[1]), "+f"(c[2]), "+f"(c[3])
        : "r"(a[0]), "r"(a[1]), "r"(a[2]), "r"(a[3]), "r"(b0), "r"(b1));
}
__device__ __forceinline__ void ldsm4(uint32_t* r, uint32_t saddr) {
    asm volatile("ldmatrix.sync.aligned.m8n8.x4.shared.b16 {%0,%1,%2,%3}, [%4];"
        : "=r"(r[0]), "=r"(r[1]), "=r"(r[2]), "=r"(r[3]) : "r"(saddr));
}
__device__ __forceinline__ void cpa16(uint32_t dst, const void* src) {
    asm volatile("cp.async.cg.shared.global [%0], [%1], 16;" :: "r"(dst), "l"(src));
}
__device__ __forceinline__ void cpa_commit() {
    asm volatile("cp.async.commit_group;");
}
template<int N>
__device__ __forceinline__ void cpa_wait() {
    asm volatile("cp.async.wait_group %0;" :: "n"(N));
}

// ---------------- converts ----------------
__global__ void cvt_x_kernel(const float4* __restrict__ src, uint4* __restrict__ dst, int n4)
{
    int i = blockIdx.x * 256 + threadIdx.x;
    if (i < n4) {
        float4 v = src[i];
        uint4 u;
        u.x = f2t(v.x); u.y = f2t(v.y); u.z = f2t(v.z); u.w = f2t(v.w);
        dst[i] = u;
    }
}

// transpose+convert all 5 weights in one launch: src [K][N] fp32 -> dst [N][K] tf32
__global__ __launch_bounds__(256)
void cvt_wT_kernel(
    const float* s0, uint32_t* d0, int K0, int N0, int t0,
    const float* s1, uint32_t* d1, int K1, int N1, int t1,
    const float* s2, uint32_t* d2, int K2, int N2, int t2,
    const float* s3, uint32_t* d3, int K3, int N3, int t3,
    const float* s4, uint32_t* d4, int K4, int N4)
{
    __shared__ uint32_t tb[32][33];
    int bx = blockIdx.x;
    const float* s; uint32_t* d; int K, N;
    if (bx < t0)              { s = s0; d = d0; K = K0; N = N0; }
    else if ((bx -= t0) < t1) { s = s1; d = d1; K = K1; N = N1; }
    else if ((bx -= t1) < t2) { s = s2; d = d2; K = K2; N = N2; }
    else if ((bx -= t2) < t3) { s = s3; d = d3; K = K3; N = N3; }
    else { bx -= t3;            s = s4; d = d4; K = K4; N = N4; }

    const int nx = N >> 5;
    const int k0 = (bx / nx) * 32, n0 = (bx % nx) * 32;
    const int tx = threadIdx.x & 31, ty = threadIdx.x >> 5;   // 32 x 8
#pragma unroll
    for (int dy = 0; dy < 32; dy += 8)
        tb[ty + dy][tx] = f2t(s[(size_t)(k0 + ty + dy) * N + n0 + tx]);
    __syncthreads();
#pragma unroll
    for (int dy = 0; dy < 32; dy += 8)
        d[(size_t)(n0 + ty + dy) * K + k0 + tx] = tb[tx][ty + dy];
}

// ---------------- mma.sync GEMM: C = A[M,K](tf32) @ Wt[N,K]^T + bias ----------------
// Block tile 128x64, BK=32, 256 threads = 8 warps (4m x 2n), warp tile 32x32.
// 2-stage cp.async, single barrier per k-tile, ldmatrix fragments, 3 CTAs/SM.
// MODE 0: fp32 out. MODE 1: tf32 pattern (scaled). MODE 2: kv_up K(bf16)/V(tf32-T) split.
// MODE 3: bf16 out (scaled).
#define A_STR 36
#define A_WORDS (128 * A_STR)             // 4608
#define B_WORDS (64 * A_STR)              // 2304
#define STAGE_WORDS (A_WORDS + B_WORDS)   // 6912
#define GEMM_SMEM (2 * STAGE_WORDS * 4)   // 55296 B

template<int MODE>
__device__ __forceinline__ void gemm_body(
    const uint32_t* __restrict__ A, const uint32_t* __restrict__ Wt,
    const float* __restrict__ bias, float* __restrict__ C,
    int N, int K, int m0, int n0, float scale, uint32_t* smg)
{
    const int tid  = threadIdx.x;
    const int lane = tid & 31;
    const int wid  = tid >> 5;
    const int wm   = (wid >> 1) * 32;
    const int wn   = (wid & 1) * 32;
    const int l4   = lane & 3;
    const int l2   = lane >> 2;

    const int ar0 = tid >> 3;
    const int ca  = (tid & 7) * 4;

    const int lrow = ((lane >> 3) & 1) * 8 + (lane & 7);
    const int lcol = (lane >> 4) * 4;
    const uint32_t smb = (uint32_t)__cvta_generic_to_shared(smg);

    float acc[2][4][4];
#pragma unroll
    for (int i = 0; i < 2; i++)
#pragma unroll
        for (int j = 0; j < 4; j++)
#pragma unroll
            for (int c = 0; c < 4; c++) acc[i][j][c] = 0.f;

    const int nk = K >> 5;

    auto issue = [&](int k0, int s) {
        uint32_t ab = smb + s * (STAGE_WORDS * 4);
        uint32_t bb = ab + A_WORDS * 4;
#pragma unroll
        for (int v = 0; v < 4; v++)
            cpa16(ab + ((ar0 + v * 32) * A_STR + ca) * 4,
                  A + (size_t)(m0 + ar0 + v * 32) * K + k0 + ca);
#pragma unroll
        for (int v = 0; v < 2; v++)
            cpa16(bb + ((ar0 + v * 32) * A_STR + ca) * 4,
                  Wt + (size_t)(n0 + ar0 + v * 32) * K + k0 + ca);
        cpa_commit();
    };

    issue(0, 0);
    for (int kt = 0; kt < nk; kt++) {
        cpa_wait<0>();
        __syncthreads();
        if (kt + 1 < nk) issue((kt + 1) << 5, (kt + 1) & 1);

        const uint32_t asb = smb + (kt & 1) * (STAGE_WORDS * 4);
        const uint32_t bsb = asb + A_WORDS * 4;

#pragma unroll
        for (int kk = 0; kk < 4; kk++) {
            const int k = kk * 8;
            uint32_t af[2][4], br[2][4];
#pragma unroll
            for (int im = 0; im < 2; im++)
                ldsm4(af[im], asb + ((wm + im * 16 + lrow) * A_STR + k + lcol) * 4);
#pragma unroll
            for (int p = 0; p < 2; p++)
                ldsm4(br[p], bsb + ((wn + p * 16 + lrow) * A_STR + k + lcol) * 4);
            uint32_t bf[4][2] = {
                {br[0][0], br[0][2]}, {br[0][1], br[0][3]},
                {br[1][0], br[1][2]}, {br[1][1], br[1][3]}};
#pragma unroll
            for (int im = 0; im < 2; im++)
#pragma unroll
                for (int in = 0; in < 4; in++)
                    mma8(acc[im][in], af[im], bf[in]);
        }
    }

#pragma unroll
    for (int im = 0; im < 2; im++) {
        int row = m0 + wm + im * 16 + l2;
#pragma unroll
        for (int in = 0; in < 4; in++) {
            int col = n0 + wn + in * 8 + 2 * l4;
            float b0 = bias[col], b1 = bias[col + 1];
            if (MODE == 0) {
                *(float2*)&C[(size_t)row * N + col] =
                    make_float2(acc[im][in][0] + b0, acc[im][in][1] + b1);
                *(float2*)&C[(size_t)(row + 8) * N + col] =
                    make_float2(acc[im][in][2] + b0, acc[im][in][3] + b1);
            } else if (MODE == 1) {
                *(float2*)&C[(size_t)row * N + col] = make_float2(
                    __uint_as_float(f2t(scale * (acc[im][in][0] + b0))),
                    __uint_as_float(f2t(scale * (acc[im][in][1] + b1))));
                *(float2*)&C[(size_t)(row + 8) * N + col] = make_float2(
                    __uint_as_float(f2t(scale * (acc[im][in][2] + b0))),
                    __uint_as_float(f2t(scale * (acc[im][in][3] + b1))));
            } else if (MODE == 3) {   // bf16 out (scaled)
                uint16_t* Cb = (uint16_t*)C;
                *(uint32_t*)&Cb[(size_t)row * N + col] =
                    bf2(scale * (acc[im][in][0] + b0), scale * (acc[im][in][1] + b1));
                *(uint32_t*)&Cb[(size_t)(row + 8) * N + col] =
                    bf2(scale * (acc[im][in][2] + b0), scale * (acc[im][in][3] + b1));
            } else {   // MODE 2: kv_up split output
                if (col < DIM) {   // K part: bf16 natural [token][DIM]
                    uint16_t* Kb = (uint16_t*)C;
                    *(uint32_t*)&Kb[(size_t)row * DIM + col] =
                        bf2(acc[im][in][0] + b0, acc[im][in][1] + b1);
                    *(uint32_t*)&Kb[(size_t)(row + 8) * DIM + col] =
                        bf2(acc[im][in][2] + b0, acc[im][in][3] + b1);
                } else {           // V part: tf32 transposed [b][d][s]
                    int d  = col - DIM;
                    int bb = row >> 11;
                    int s  = row & (SEQ - 1);
                    uint32_t* v0 = g_vt + ((size_t)bb * DIM + d) * SEQ + s;
                    v0[0]       = f2t(acc[im][in][0] + b0);
                    v0[SEQ]     = f2t(acc[im][in][1] + b1);
                    v0[8]       = f2t(acc[im][in][2] + b0);
                    v0[SEQ + 8] = f2t(acc[im][in][3] + b1);
                }
            }
        }
    }
}

template<int MODE>
__global__ __launch_bounds__(256, 3)
void gemm_tt_kernel(const uint32_t* __restrict__ A, const uint32_t* __restrict__ Wt,
                    const float* __restrict__ bias, float* __restrict__ C,
                    int N, int K, float scale)
{
    extern __shared__ uint32_t smg[];
    gemm_body<MODE>(A, Wt, bias, C, N, K, blockIdx.y * 128, blockIdx.x * 64, scale, smg);
}

// fused kv_latent (N=128 -> 2 n-tiles) + q_c (N=256 -> 4 n-tiles): grid.x = 6
__global__ __launch_bounds__(256, 3)
void fused_latqc_kernel(const uint32_t* __restrict__ X,
                        const uint32_t* __restrict__ WkvcT, const float* __restrict__ bkvc, float* __restrict__ lat,
                        const uint32_t* __restrict__ WqcT,  const float* __restrict__ bqc,  float* __restrict__ qc)
{
    extern __shared__ uint32_t smg[];
    const int bx = blockIdx.x;
    if (bx < 2)
        gemm_body<1>(X, WkvcT, bkvc, lat, LATENT, DIM, blockIdx.y * 128, bx * 64, 1.f, smg);
    else
        gemm_body<1>(X, WqcT, bqc, qc, QRANK, DIM, blockIdx.y * 128, (bx - 2) * 64, 1.f, smg);
}

// fused kv_up (MODE2: K bf16 + V tf32-T) + q_up (MODE3: bf16 Q, pre-scaled)
__global__ __launch_bounds__(256, 3)
void fused_kvq_kernel(const uint32_t* __restrict__ Lat, const uint32_t* __restrict__ WkvuT,
                      const float* __restrict__ bkvu, float* __restrict__ Kout,
                      const uint32_t* __restrict__ Qc, const uint32_t* __restrict__ WquT,
                      const float* __restrict__ bqu, float* __restrict__ Qout)
{
    extern __shared__ uint32_t smg[];
    const int bx = blockIdx.x;
    if (bx < 32)
        gemm_body<2>(Lat, WkvuT, bkvu, Kout, 2 * DIM, LATENT, blockIdx.y * 128, bx * 64, 1.f, smg);
    else
        gemm_body<3>(Qc, WquT, bqu, Qout, DIM, QRANK, blockIdx.y * 128, (bx - 32) * 64, QSCALE, smg);
}

// ---------------- causal flash attention: bf16 QK, tf32 PV, hd=64 ----------------
// BQ=128 q rows/CTA, 8 warps; kv tile 64, register-prefetch double buffer.
// Q/K bf16 natural rows (stride 72 b16 = 144B, 36 words % 32 == 4 -> conflict-free ldsm).
// V tf32 [d][kv] + b32-ldsm (proven); P tf32 permuted (proven).
#define BQ     128
#define QSTRH  72    // b16 units
#define VSTR   68    // u32 units
#define PSTR   72    // u32 units
#define FL_SMEM (BQ * QSTRH * 2 + 64 * QSTRH * 2 + 64 * VSTR * 4 + BQ * PSTR * 4)  // 81920 B

__global__ __launch_bounds__(256, 2)
void flash_kernel(const uint16_t* __restrict__ Q, const uint16_t* __restrict__ Kp,
                  const uint32_t* __restrict__ Vt, float* __restrict__ Ctx)
{
    extern __shared__ uint32_t sm[];
    uint16_t* Qs = (uint16_t*)sm;          // [BQ][QSTRH] bf16 natural [q][d]
    uint16_t* Ks = Qs + BQ * QSTRH;        // [64][QSTRH] bf16 natural [kv][d]
    uint32_t* Vs = (uint32_t*)(Ks + 64 * QSTRH);   // [64][VSTR] tf32 [d][kv]
    uint32_t* Ps = Vs + 64 * VSTR;         // [BQ][PSTR] tf32 permuted

    const int qt = (gridDim.x - 1) - blockIdx.x;  // longest CTAs first
    const int h  = blockIdx.y;
    const int b  = blockIdx.z;
    const int q0 = qt * BQ;
    const int tid  = threadIdx.x;
    const int lane = tid & 31;
    const int w    = tid >> 5;
    const int l4   = lane & 3;
    const int l2   = lane >> 2;
    const int lrow0 = w * 16 + l2;
    const int lrow1 = lrow0 + 8;

    // b32-ldsm lane addressing (V path, proven)
    const int lrow = ((lane >> 3) & 1) * 8 + (lane & 7);
    const int lcol = (lane >> 4) * 4;
    // b16-ldsm lane addressing (Q/K path)
    const int lq  = lane >> 3;       // quad 0..3
    const int l7  = lane & 7;
    const uint32_t qsb = (uint32_t)__cvta_generic_to_shared(Qs);
    const uint32_t ksb = (uint32_t)__cvta_generic_to_shared(Ks);
    const uint32_t vsb = (uint32_t)__cvta_generic_to_shared(Vs);
    // A-frag (m16n8k16): m0=(r0-7,k0-7) m1=(r8-15,k0-7) m2=(r0-7,k8-15) m3=(r8-15,k8-15)
    const uint32_t qa_lane = (uint32_t)((w * 16 + (lq & 1) * 8 + l7) * (QSTRH * 2) + (lq >> 1) * 16);
    // B-frag x4 -> two n-groups: m0=(n0-7,k0-7) m1=(n0-7,k8-15) m2=(n8-15,k0-7) m3=(n8-15,k8-15)
    const uint32_t kb_lane = (uint32_t)(((lq >> 1) * 8 + l7) * (QSTRH * 2) + (lq & 1) * 16);

    // ---- load Q (bf16, pre-scaled) natural ----
    const size_t qbase = ((size_t)(b * SEQ + q0)) * DIM + h * HDIM;
#pragma unroll
    for (int v = 0; v < 4; v++) {
        int i = tid + v * 256;
        int r = i >> 3, cv = i & 7;
        uint4 qv = *(const uint4*)(Q + qbase + (size_t)r * DIM + cv * 8);
        *(uint4*)(Qs + r * QSTRH + cv * 8) = qv;
    }

    float mr0 = -1.0e30f, mr1 = -1.0e30f, lr0 = 0.f, lr1 = 0.f;
    float oacc[8][4];
#pragma unroll
    for (int n = 0; n < 8; n++)
#pragma unroll
        for (int c = 0; c < 4; c++) oacc[n][c] = 0.f;

    const int ntiles = 2 * qt + 2;
    uint4 kreg[2], vreg[4];

    auto gload = [&](int kt) {
        const size_t kb = ((size_t)(b * SEQ + kt * 64)) * DIM + h * HDIM;
        const size_t vb = ((size_t)(b * DIM + h * HDIM)) * SEQ + kt * 64;
#pragma unroll
        for (int v = 0; v < 2; v++) {
            int i = tid + v * 256;
            int r = i >> 3, cv = i & 7;
            kreg[v] = *(const uint4*)(Kp + kb + (size_t)r * DIM + cv * 8);
        }
#pragma unroll
        for (int v = 0; v < 4; v++) {
            int i = tid + v * 256;
            int r = i >> 4, cv = i & 15;
            vreg[v] = *(const uint4*)(Vt + vb + (size_t)r * SEQ + cv * 4);
        }
    };

    gload(0);

    for (int kt = 0; kt < ntiles; kt++) {
        __syncthreads();
#pragma unroll
        for (int v = 0; v < 2; v++) {
            int i = tid + v * 256;
            int r = i >> 3, cv = i & 7;
            *(uint4*)(Ks + r * QSTRH + cv * 8) = kreg[v];
        }
#pragma unroll
        for (int v = 0; v < 4; v++) {
            int i = tid + v * 256;
            int r = i >> 4, cv = i & 15;
            *(uint4*)(Vs + r * VSTR + cv * 4) = vreg[v];
        }
        __syncthreads();

        if (kt + 1 < ntiles) gload(kt + 1);

        const int k0 = kt * 64;
        const bool active = (k0 <= q0 + w * 16 + 15);
        if (active) {
            // ---- S = Q K^T, bf16 m16n8k16 ----
            float sacc[8][4];
#pragma unroll
            for (int n = 0; n < 8; n++)
#pragma unroll
                for (int c = 0; c < 4; c++) sacc[n][c] = 0.f;

#pragma unroll
            for (int kc = 0; kc < 4; kc++) {
                uint32_t a[4];
                ldsm4(a, qsb + qa_lane + kc * 32);
#pragma unroll
                for (int p = 0; p < 4; p++) {
                    uint32_t kr[4];
                    ldsm4(kr, ksb + kb_lane + (uint32_t)(p * 16 * (QSTRH * 2)) + kc * 32);
                    mma16(sacc[2 * p],     a, kr[0], kr[1]);
                    mma16(sacc[2 * p + 1], a, kr[2], kr[3]);
                }
            }

            // ---- causal mask ----
            if (k0 + 63 > q0 + w * 16) {
                const int g0 = q0 + lrow0, g1 = q0 + lrow1;
#pragma unroll
                for (int n = 0; n < 8; n++) {
                    int cg = k0 + n * 8 + 2 * l4;
                    if (cg     > g0) sacc[n][0] = -1.0e30f;
                    if (cg + 1 > g0) sacc[n][1] = -1.0e30f;
                    if (cg     > g1) sacc[n][2] = -1.0e30f;
                    if (cg + 1 > g1) sacc[n][3] = -1.0e30f;
                }
            }

            // ---- online softmax (log2 domain) ----
            float mx0 = -1.0e30f, mx1 = -1.0e30f;
#pragma unroll
            for (int n = 0; n < 8; n++) {
                mx0 = fmaxf(mx0, fmaxf(sacc[n][0], sacc[n][1]));
                mx1 = fmaxf(mx1, fmaxf(sacc[n][2], sacc[n][3]));
            }
            mx0 = fmaxf(mx0, __shfl_xor_sync(0xffffffffu, mx0, 1));
            mx0 = fmaxf(mx0, __shfl_xor_sync(0xffffffffu, mx0, 2));
            mx1 = fmaxf(mx1, __shfl_xor_sync(0xffffffffu, mx1, 1));
            mx1 = fmaxf(mx1, __shfl_xor_sync(0xffffffffu, mx1, 2));

            float mn0 = fmaxf(mr0, mx0), mn1 = fmaxf(mr1, mx1);
            float al0 = ex2(mr0 - mn0),  al1 = ex2(mr1 - mn1);
            float s0 = 0.f, s1 = 0.f;
#pragma unroll
            for (int n = 0; n < 8; n++) {
                float p0 = ex2(sacc[n][0] - mn0);
                float p1 = ex2(sacc[n][1] - mn0);
                float p2 = ex2(sacc[n][2] - mn1);
                float p3 = ex2(sacc[n][3] - mn1);
                sacc[n][0] = p0; sacc[n][1] = p1; sacc[n][2] = p2; sacc[n][3] = p3;
                s0 += p0 + p1;
                s1 += p2 + p3;
            }
            s0 += __shfl_xor_sync(0xffffffffu, s0, 1);
            s0 += __shfl_xor_sync(0xffffffffu, s0, 2);
            s1 += __shfl_xor_sync(0xffffffffu, s1, 1);
            s1 += __shfl_xor_sync(0xffffffffu, s1, 2);
            lr0 = lr0 * al0 + s0;
            lr1 = lr1 * al1 + s1;
            mr0 = mn0; mr1 = mn1;

#pragma unroll
            for (int n = 0; n < 8; n++) {
                oacc[n][0] *= al0; oacc[n][1] *= al0;
                oacc[n][2] *= al1; oacc[n][3] *= al1;
            }

            // ---- write P (tf32, permuted, warp-private rows) ----
            const int p0off = (l4 < 2) ? 4 * l4 : 4 * l4 - 7;
#pragma unroll
            for (int n = 0; n < 8; n++) {
                uint32_t* r0p = Ps + lrow0 * PSTR + n * 8 + p0off;
                uint32_t* r1p = Ps + lrow1 * PSTR + n * 8 + p0off;
                r0p[0] = f2t(sacc[n][0]); r0p[2] = f2t(sacc[n][1]);
                r1p[0] = f2t(sacc[n][2]); r1p[2] = f2t(sacc[n][3]);
            }
            __syncwarp();

            // ---- O += P @ V, tf32 m16n8k8 (V via b32-ldsm on transposed V) ----
#pragma unroll
            for (int kk = 0; kk < 8; kk++) {
                uint2 a01 = *(const uint2*)(Ps + lrow0 * PSTR + kk * 8 + 2 * l4);
                uint2 a23 = *(const uint2*)(Ps + lrow1 * PSTR + kk * 8 + 2 * l4);
                uint32_t a[4] = {a01.x, a23.x, a01.y, a23.y};
#pragma unroll
                for (int p = 0; p < 4; p++) {
                    uint32_t vr[4];
                    ldsm4(vr, vsb + ((p * 16 + lrow) * VSTR + kk * 8 + lcol) * 4);
                    uint32_t b0[2] = {vr[0], vr[2]};
                    uint32_t b1[2] = {vr[1], vr[3]};
                    mma8(oacc[2 * p],     a, b0);
                    mma8(oacc[2 * p + 1], a, b1);
                }
            }
            __syncwarp();
        }
    }

    const float inv0 = 1.f / lr0, inv1 = 1.f / lr1;
    const size_t ob0 = ((size_t)(b * SEQ + q0 + lrow0)) * DIM + h * HDIM;
    const size_t ob1 = ((size_t)(b * SEQ + q0 + lrow1)) * DIM + h * HDIM;
#pragma unroll
    for (int n = 0; n < 8; n++) {
        int col = n * 8 + 2 * l4;
        *(float2*)&Ctx[ob0 + col] = make_float2(__uint_as_float(f2t(oacc[n][0] * inv0)),
                                                __uint_as_float(f2t(oacc[n][1] * inv0)));
        *(float2*)&Ctx[ob1 + col] = make_float2(__uint_as_float(f2t(oacc[n][2] * inv1)),
                                                __uint_as_float(f2t(oacc[n][3] * inv1)));
    }
}

// ---------------- host launcher ----------------
extern "C" void kernel_launch(void* const* d_in, const int* in_sizes, int n_in,
                              void* d_out, int out_size)
{
    const float* x     = (const float*)d_in[0];
    // d_in[1] = mask (causal, hard-coded)
    const float* w_kvc = (const float*)d_in[2];
    const float* b_kvc = (const float*)d_in[3];
    const float* w_kvu = (const float*)d_in[4];
    const float* b_kvu = (const float*)d_in[5];
    const float* w_qc  = (const float*)d_in[6];
    const float* b_qc  = (const float*)d_in[7];
    const float* w_qu  = (const float*)d_in[8];
    const float* b_qu  = (const float*)d_in[9];
    const float* w_o   = (const float*)d_in[10];
    const float* b_o   = (const float*)d_in[11];
    float* out = (float*)d_out;

    float *lat, *qc, *ctx;
    uint16_t *kb, *qb;
    uint32_t *vt, *xt, *wkvc, *wqc, *wkvu, *wqu, *wo;
    cudaGetSymbolAddress((void**)&lat,  g_lat);
    cudaGetSymbolAddress((void**)&kb,   g_kb);
    cudaGetSymbolAddress((void**)&vt,   g_vt);
    cudaGetSymbolAddress((void**)&qc,   g_qc);
    cudaGetSymbolAddress((void**)&qb,   g_qb);
    cudaGetSymbolAddress((void**)&ctx,  g_ctx);
    cudaGetSymbolAddress((void**)&xt,   g_xt);
    cudaGetSymbolAddress((void**)&wkvc, g_wkvc);
    cudaGetSymbolAddress((void**)&wqc,  g_wqc);
    cudaGetSymbolAddress((void**)&wkvu, g_wkvu);
    cudaGetSymbolAddress((void**)&wqu,  g_wqu);
    cudaGetSymbolAddress((void**)&wo,   g_wo);

    cudaFuncSetAttribute(gemm_tt_kernel<0>, cudaFuncAttributeMaxDynamicSharedMemorySize, GEMM_SMEM);
    cudaFuncSetAttribute(fused_latqc_kernel, cudaFuncAttributeMaxDynamicSharedMemorySize, GEMM_SMEM);
    cudaFuncSetAttribute(fused_kvq_kernel, cudaFuncAttributeMaxDynamicSharedMemorySize, GEMM_SMEM);
    cudaFuncSetAttribute(flash_kernel, cudaFuncAttributeMaxDynamicSharedMemorySize, FL_SMEM);

    const int t0 = (DIM / 32) * (LATENT / 32);
    const int t1 = (DIM / 32) * (QRANK / 32);
    const int t2 = (LATENT / 32) * (2 * DIM / 32);
    const int t3 = (QRANK / 32) * (DIM / 32);
    const int t4 = (DIM / 32) * (DIM / 32);
    cvt_wT_kernel<<<t0 + t1 + t2 + t3 + t4, 256>>>(
        w_kvc, wkvc, DIM, LATENT, t0,
        w_qc,  wqc,  DIM, QRANK,  t1,
        w_kvu, wkvu, LATENT, 2 * DIM, t2,
        w_qu,  wqu,  QRANK, DIM, t3,
        w_o,   wo,   DIM, DIM);
    cvt_x_kernel<<<(T_TOK * DIM / 4 + 255) / 256, 256>>>((const float4*)x, (uint4*)xt, T_TOK * DIM / 4);

    // fused kv_latent + q_c  (tf32 out)
    fused_latqc_kernel<<<dim3(6, T_TOK / 128), 256, GEMM_SMEM>>>(
        xt, wkvc, b_kvc, lat, wqc, b_qc, qc);
    // fused kv_up (K bf16 + V tf32-T) + q_up (Q bf16, pre-scaled)
    fused_kvq_kernel<<<dim3(48, T_TOK / 128), 256, GEMM_SMEM>>>(
        (const uint32_t*)lat, wkvu, b_kvu, (float*)kb,
        (const uint32_t*)qc, wqu, b_qu, (float*)qb);
    // causal flash attention -> ctx (tf32-out)
    flash_kernel<<<dim3(SEQ / BQ, NHEADS, NBATCH), 256, FL_SMEM>>>(
        qb, kb, vt, ctx);
    // out = ctx @ w_o + b  (fp32 out)
    gemm_tt_kernel<0><<<dim3(DIM / 64, T_TOK / 128), 256, GEMM_SMEM>>>(
        (const uint32_t*)ctx, wo, b_o, out, DIM, DIM, 1.f);
}

// round 16
// speedup vs baseline: 1.4566x; 1.2480x over previous
#include <cuda_runtime.h>
#include <cuda_bf16.h>
#include <cuda_fp16.h>
#include <cstdint>

// ---------------- problem constants ----------------
#define T_TOK   8192      // B*S
#define SEQ     2048
#define NBATCH  4
#define DIM     1024
#define NHEADS  16
#define HDIM    64
#define LATENT  128
#define QRANK   256

#define QSCALE  0.18033688011112042f   // (1/sqrt(64)) * log2(e)

// ---------------- scratch (device globals; no allocation) ----------------
__device__ float g_lat [T_TOK * LATENT];        // tf32 patterns
__device__ uint16_t g_kb[T_TOK * DIM];          // K as bf16, natural [token][DIM]
__device__ uint16_t g_vh[(size_t)NBATCH * DIM * SEQ];  // V as fp16, transposed [b][d][s]
__device__ float g_qc  [T_TOK * QRANK];         // tf32 patterns
__device__ uint16_t g_qb[T_TOK * DIM];          // Q as bf16, pre-scaled by QSCALE
__device__ float g_ctx [T_TOK * DIM];           // tf32 patterns
__device__ uint32_t g_xt  [T_TOK * DIM];        // x as tf32
__device__ uint32_t g_wkvc[DIM * LATENT];       // transposed: [LATENT][DIM]
__device__ uint32_t g_wqc [DIM * QRANK];        // transposed: [QRANK][DIM]
__device__ uint32_t g_wkvu[LATENT * 2 * DIM];   // transposed: [2*DIM][LATENT]
__device__ uint32_t g_wqu [QRANK * DIM];        // transposed: [DIM][QRANK]
__device__ uint32_t g_wo  [DIM * DIM];          // transposed: [DIM][DIM]

// ---------------- helpers ----------------
__device__ __forceinline__ uint32_t f2t(float x) {
    uint32_t u;
    asm("cvt.rna.tf32.f32 %0, %1;" : "=r"(u) : "f"(x));
    return u;
}
__device__ __forceinline__ uint32_t bf2(float lo, float hi) {   // pack {lo, hi} as bf16x2
    uint32_t r;
    asm("cvt.rn.bf16x2.f32 %0, %1, %2;" : "=r"(r) : "f"(hi), "f"(lo));
    return r;
}
__device__ __forceinline__ uint32_t hf2(float lo, float hi) {   // pack {lo, hi} as fp16x2
    uint32_t r;
    asm("cvt.rn.f16x2.f32 %0, %1, %2;" : "=r"(r) : "f"(hi), "f"(lo));
    return r;
}
__device__ __forceinline__ uint16_t hf1(float x) {
    uint16_t r;
    asm("cvt.rn.f16.f32 %0, %1;" : "=h"(r) : "f"(x));
    return r;
}
__device__ __forceinline__ float ex2(float x) {
    float r;
    asm("ex2.approx.f32 %0, %1;" : "=f"(r) : "f"(x));
    return r;
}
__device__ __forceinline__ void mma8(float* c, const uint32_t* a, const uint32_t* b) {
    asm volatile(
        "mma.sync.aligned.m16n8k8.row.col.f32.tf32.tf32.f32 "
        "{%0,%1,%2,%3}, {%4,%5,%6,%7}, {%8,%9}, {%0,%1,%2,%3};"
        : "+f"(c[0]), "+f"(c[1]), "+f"(c[2]), "+f"(c[3])
        : "r"(a[0]), "r"(a[1]), "r"(a[2]), "r"(a[3]), "r"(b[0]), "r"(b[1]));
}
__device__ __forceinline__ void mma16b(float* c, const uint32_t* a, uint32_t b0, uint32_t b1) {
    asm volatile(
        "mma.sync.aligned.m16n8k16.row.col.f32.bf16.bf16.f32 "
        "{%0,%1,%2,%3}, {%4,%5,%6,%7}, {%8,%9}, {%0,%1,%2,%3};"
        : "+f"(c[0]), "+f"(c[1]), "+f"(c[2]), "+f"(c[3])
        : "r"(a[0]), "r"(a[1]), "r"(a[2]), "r"(a[3]), "r"(b0), "r"(b1));
}
__device__ __forceinline__ void mma16h(float* c, const uint32_t* a, uint32_t b0, uint32_t b1) {
    asm volatile(
        "mma.sync.aligned.m16n8k16.row.col.f32.f16.f16.f32 "
        "{%0,%1,%2,%3}, {%4,%5,%6,%7}, {%8,%9}, {%0,%1,%2,%3};"
        : "+f"(c[0]), "+f"(c[1]), "+f"(c[2]), "+f"(c[3])
        : "r"(a[0]), "r"(a[1]), "r"(a[2]), "r"(a[3]), "r"(b0), "r"(b1));
}
__device__ __forceinline__ void ldsm4(uint32_t* r, uint32_t saddr) {
    asm volatile("ldmatrix.sync.aligned.m8n8.x4.shared.b16 {%0,%1,%2,%3}, [%4];"
        : "=r"(r[0]), "=r"(r[1]), "=r"(r[2]), "=r"(r[3]) : "r"(saddr));
}
__device__ __forceinline__ void cpa16(uint32_t dst, const void* src) {
    asm volatile("cp.async.cg.shared.global [%0], [%1], 16;" :: "r"(dst), "l"(src));
}
__device__ __forceinline__ void cpa_commit() {
    asm volatile("cp.async.commit_group;");
}
template<int N>
__device__ __forceinline__ void cpa_wait() {
    asm volatile("cp.async.wait_group %0;" :: "n"(N));
}

// ---------------- converts ----------------
__global__ void cvt_x_kernel(const float4* __restrict__ src, uint4* __restrict__ dst, int n4)
{
    int i = blockIdx.x * 256 + threadIdx.x;
    if (i < n4) {
        float4 v = src[i];
        uint4 u;
        u.x = f2t(v.x); u.y = f2t(v.y); u.z = f2t(v.z); u.w = f2t(v.w);
        dst[i] = u;
    }
}

// transpose+convert all 5 weights in one launch: src [K][N] fp32 -> dst [N][K] tf32
__global__ __launch_bounds__(256)
void cvt_wT_kernel(
    const float* s0, uint32_t* d0, int K0, int N0, int t0,
    const float* s1, uint32_t* d1, int K1, int N1, int t1,
    const float* s2, uint32_t* d2, int K2, int N2, int t2,
    const float* s3, uint32_t* d3, int K3, int N3, int t3,
    const float* s4, uint32_t* d4, int K4, int N4)
{
    __shared__ uint32_t tb[32][33];
    int bx = blockIdx.x;
    const float* s; uint32_t* d; int K, N;
    if (bx < t0)              { s = s0; d = d0; K = K0; N = N0; }
    else if ((bx -= t0) < t1) { s = s1; d = d1; K = K1; N = N1; }
    else if ((bx -= t1) < t2) { s = s2; d = d2; K = K2; N = N2; }
    else if ((bx -= t2) < t3) { s = s3; d = d3; K = K3; N = N3; }
    else { bx -= t3;            s = s4; d = d4; K = K4; N = N4; }

    const int nx = N >> 5;
    const int k0 = (bx / nx) * 32, n0 = (bx % nx) * 32;
    const int tx = threadIdx.x & 31, ty = threadIdx.x >> 5;   // 32 x 8
#pragma unroll
    for (int dy = 0; dy < 32; dy += 8)
        tb[ty + dy][tx] = f2t(s[(size_t)(k0 + ty + dy) * N + n0 + tx]);
    __syncthreads();
#pragma unroll
    for (int dy = 0; dy < 32; dy += 8)
        d[(size_t)(n0 + ty + dy) * K + k0 + tx] = tb[tx][ty + dy];
}

// ---------------- mma.sync GEMM: C = A[M,K](tf32) @ Wt[N,K]^T + bias ----------------
// Block tile 128x64, BK=32, 256 threads = 8 warps (4m x 2n), warp tile 32x32.
// 2-stage cp.async, single barrier per k-tile, ldmatrix fragments, 3 CTAs/SM.
// MODE 0: fp32 out. MODE 1: tf32 pattern (scaled). MODE 2: kv_up K(bf16)/V(fp16-T) split.
// MODE 3: bf16 out (scaled).
#define A_STR 36
#define A_WORDS (128 * A_STR)             // 4608
#define B_WORDS (64 * A_STR)              // 2304
#define STAGE_WORDS (A_WORDS + B_WORDS)   // 6912
#define GEMM_SMEM (2 * STAGE_WORDS * 4)   // 55296 B

template<int MODE>
__device__ __forceinline__ void gemm_body(
    const uint32_t* __restrict__ A, const uint32_t* __restrict__ Wt,
    const float* __restrict__ bias, float* __restrict__ C,
    int N, int K, int m0, int n0, float scale, uint32_t* smg)
{
    const int tid  = threadIdx.x;
    const int lane = tid & 31;
    const int wid  = tid >> 5;
    const int wm   = (wid >> 1) * 32;
    const int wn   = (wid & 1) * 32;
    const int l4   = lane & 3;
    const int l2   = lane >> 2;

    const int ar0 = tid >> 3;
    const int ca  = (tid & 7) * 4;

    const int lrow = ((lane >> 3) & 1) * 8 + (lane & 7);
    const int lcol = (lane >> 4) * 4;
    const uint32_t smb = (uint32_t)__cvta_generic_to_shared(smg);

    float acc[2][4][4];
#pragma unroll
    for (int i = 0; i < 2; i++)
#pragma unroll
        for (int j = 0; j < 4; j++)
#pragma unroll
            for (int c = 0; c < 4; c++) acc[i][j][c] = 0.f;

    const int nk = K >> 5;

    auto issue = [&](int k0, int s) {
        uint32_t ab = smb + s * (STAGE_WORDS * 4);
        uint32_t bb = ab + A_WORDS * 4;
#pragma unroll
        for (int v = 0; v < 4; v++)
            cpa16(ab + ((ar0 + v * 32) * A_STR + ca) * 4,
                  A + (size_t)(m0 + ar0 + v * 32) * K + k0 + ca);
#pragma unroll
        for (int v = 0; v < 2; v++)
            cpa16(bb + ((ar0 + v * 32) * A_STR + ca) * 4,
                  Wt + (size_t)(n0 + ar0 + v * 32) * K + k0 + ca);
        cpa_commit();
    };

    issue(0, 0);
    for (int kt = 0; kt < nk; kt++) {
        cpa_wait<0>();
        __syncthreads();
        if (kt + 1 < nk) issue((kt + 1) << 5, (kt + 1) & 1);

        const uint32_t asb = smb + (kt & 1) * (STAGE_WORDS * 4);
        const uint32_t bsb = asb + A_WORDS * 4;

#pragma unroll
        for (int kk = 0; kk < 4; kk++) {
            const int k = kk * 8;
            uint32_t af[2][4], br[2][4];
#pragma unroll
            for (int im = 0; im < 2; im++)
                ldsm4(af[im], asb + ((wm + im * 16 + lrow) * A_STR + k + lcol) * 4);
#pragma unroll
            for (int p = 0; p < 2; p++)
                ldsm4(br[p], bsb + ((wn + p * 16 + lrow) * A_STR + k + lcol) * 4);
            uint32_t bf[4][2] = {
                {br[0][0], br[0][2]}, {br[0][1], br[0][3]},
                {br[1][0], br[1][2]}, {br[1][1], br[1][3]}};
#pragma unroll
            for (int im = 0; im < 2; im++)
#pragma unroll
                for (int in = 0; in < 4; in++)
                    mma8(acc[im][in], af[im], bf[in]);
        }
    }

#pragma unroll
    for (int im = 0; im < 2; im++) {
        int row = m0 + wm + im * 16 + l2;
#pragma unroll
        for (int in = 0; in < 4; in++) {
            int col = n0 + wn + in * 8 + 2 * l4;
            float b0 = bias[col], b1 = bias[col + 1];
            if (MODE == 0) {
                *(float2*)&C[(size_t)row * N + col] =
                    make_float2(acc[im][in][0] + b0, acc[im][in][1] + b1);
                *(float2*)&C[(size_t)(row + 8) * N + col] =
                    make_float2(acc[im][in][2] + b0, acc[im][in][3] + b1);
            } else if (MODE == 1) {
                *(float2*)&C[(size_t)row * N + col] = make_float2(
                    __uint_as_float(f2t(scale * (acc[im][in][0] + b0))),
                    __uint_as_float(f2t(scale * (acc[im][in][1] + b1))));
                *(float2*)&C[(size_t)(row + 8) * N + col] = make_float2(
                    __uint_as_float(f2t(scale * (acc[im][in][2] + b0))),
                    __uint_as_float(f2t(scale * (acc[im][in][3] + b1))));
            } else if (MODE == 3) {   // bf16 out (scaled)
                uint16_t* Cb = (uint16_t*)C;
                *(uint32_t*)&Cb[(size_t)row * N + col] =
                    bf2(scale * (acc[im][in][0] + b0), scale * (acc[im][in][1] + b1));
                *(uint32_t*)&Cb[(size_t)(row + 8) * N + col] =
                    bf2(scale * (acc[im][in][2] + b0), scale * (acc[im][in][3] + b1));
            } else {   // MODE 2: kv_up split output
                if (col < DIM) {   // K part: bf16 natural [token][DIM]
                    uint16_t* Kb = (uint16_t*)C;
                    *(uint32_t*)&Kb[(size_t)row * DIM + col] =
                        bf2(acc[im][in][0] + b0, acc[im][in][1] + b1);
                    *(uint32_t*)&Kb[(size_t)(row + 8) * DIM + col] =
                        bf2(acc[im][in][2] + b0, acc[im][in][3] + b1);
                } else {           // V part: fp16 transposed [b][d][s]
                    int d  = col - DIM;
                    int bb = row >> 11;
                    int s  = row & (SEQ - 1);
                    uint16_t* v0 = g_vh + ((size_t)bb * DIM + d) * SEQ + s;
                    v0[0]       = hf1(acc[im][in][0] + b0);
                    v0[SEQ]     = hf1(acc[im][in][1] + b1);
                    v0[8]       = hf1(acc[im][in][2] + b0);
                    v0[SEQ + 8] = hf1(acc[im][in][3] + b1);
                }
            }
        }
    }
}

template<int MODE>
__global__ __launch_bounds__(256, 3)
void gemm_tt_kernel(const uint32_t* __restrict__ A, const uint32_t* __restrict__ Wt,
                    const float* __restrict__ bias, float* __restrict__ C,
                    int N, int K, float scale)
{
    extern __shared__ uint32_t smg[];
    gemm_body<MODE>(A, Wt, bias, C, N, K, blockIdx.y * 128, blockIdx.x * 64, scale, smg);
}

// fused kv_latent (N=128 -> 2 n-tiles) + q_c (N=256 -> 4 n-tiles): grid.x = 6
__global__ __launch_bounds__(256, 3)
void fused_latqc_kernel(const uint32_t* __restrict__ X,
                        const uint32_t* __restrict__ WkvcT, const float* __restrict__ bkvc, float* __restrict__ lat,
                        const uint32_t* __restrict__ WqcT,  const float* __restrict__ bqc,  float* __restrict__ qc)
{
    extern __shared__ uint32_t smg[];
    const int bx = blockIdx.x;
    if (bx < 2)
        gemm_body<1>(X, WkvcT, bkvc, lat, LATENT, DIM, blockIdx.y * 128, bx * 64, 1.f, smg);
    else
        gemm_body<1>(X, WqcT, bqc, qc, QRANK, DIM, blockIdx.y * 128, (bx - 2) * 64, 1.f, smg);
}

// fused kv_up (MODE2: K bf16 + V fp16-T) + q_up (MODE3: bf16 Q, pre-scaled)
__global__ __launch_bounds__(256, 3)
void fused_kvq_kernel(const uint32_t* __restrict__ Lat, const uint32_t* __restrict__ WkvuT,
                      const float* __restrict__ bkvu, float* __restrict__ Kout,
                      const uint32_t* __restrict__ Qc, const uint32_t* __restrict__ WquT,
                      const float* __restrict__ bqu, float* __restrict__ Qout)
{
    extern __shared__ uint32_t smg[];
    const int bx = blockIdx.x;
    if (bx < 32)
        gemm_body<2>(Lat, WkvuT, bkvu, Kout, 2 * DIM, LATENT, blockIdx.y * 128, bx * 64, 1.f, smg);
    else
        gemm_body<3>(Qc, WquT, bqu, Qout, DIM, QRANK, blockIdx.y * 128, (bx - 32) * 64, QSCALE, smg);
}

// ---------------- causal flash attention: bf16 QK, fp16 PV, hd=64 ----------------
// BQ=128 q rows/CTA, 8 warps; kv tile 64, register-prefetch double buffer.
// All 16-bit smem rows stride 72 b16 (144B; 36 words % 32 == 4 -> conflict-free b16 ldsm).
// Q/K bf16 natural [q|kv][d]; V fp16 natural [d][kv]; P fp16 natural [q][kv].
#define BQ     128
#define STRH   72    // b16 units, all four tiles
#define FL_SMEM ((BQ + 64 + 64 + BQ) * STRH * 2)   // 55296 B

__global__ __launch_bounds__(256, 2)
void flash_kernel(const uint16_t* __restrict__ Q, const uint16_t* __restrict__ Kp,
                  const uint16_t* __restrict__ Vh, float* __restrict__ Ctx)
{
    extern __shared__ uint32_t sm[];
    uint16_t* Qs = (uint16_t*)sm;          // [BQ][STRH] bf16 [q][d]
    uint16_t* Ks = Qs + BQ * STRH;         // [64][STRH] bf16 [kv][d]
    uint16_t* Vs = Ks + 64 * STRH;         // [64][STRH] fp16 [d][kv]
    uint16_t* Ps = Vs + 64 * STRH;         // [BQ][STRH] fp16 [q][kv]

    const int qt = (gridDim.x - 1) - blockIdx.x;  // longest CTAs first
    const int h  = blockIdx.y;
    const int b  = blockIdx.z;
    const int q0 = qt * BQ;
    const int tid  = threadIdx.x;
    const int lane = tid & 31;
    const int w    = tid >> 5;
    const int l4   = lane & 3;
    const int l2   = lane >> 2;
    const int lrow0 = w * 16 + l2;
    const int lrow1 = lrow0 + 8;

    // b16-ldsm lane addressing
    const int lq  = lane >> 3;       // quad 0..3
    const int l7  = lane & 7;
    const uint32_t qsb = (uint32_t)__cvta_generic_to_shared(Qs);
    const uint32_t ksb = (uint32_t)__cvta_generic_to_shared(Ks);
    const uint32_t vsb = (uint32_t)__cvta_generic_to_shared(Vs);
    const uint32_t psb = (uint32_t)__cvta_generic_to_shared(Ps);
    // A-frag (m16n8k16): m0=(r0-7,k0-7) m1=(r8-15,k0-7) m2=(r0-7,k8-15) m3=(r8-15,k8-15)
    const uint32_t a_lane = (uint32_t)((w * 16 + (lq & 1) * 8 + l7) * (STRH * 2) + (lq >> 1) * 16);
    // B-frag x4: m0=(n0-7,k0-7) m1=(n0-7,k8-15) m2=(n8-15,k0-7) m3=(n8-15,k8-15)
    const uint32_t b_lane = (uint32_t)(((lq >> 1) * 8 + l7) * (STRH * 2) + (lq & 1) * 16);

    // ---- load Q (bf16, pre-scaled) natural ----
    const size_t qbase = ((size_t)(b * SEQ + q0)) * DIM + h * HDIM;
#pragma unroll
    for (int v = 0; v < 4; v++) {
        int i = tid + v * 256;
        int r = i >> 3, cv = i & 7;
        uint4 qv = *(const uint4*)(Q + qbase + (size_t)r * DIM + cv * 8);
        *(uint4*)(Qs + r * STRH + cv * 8) = qv;
    }

    float mr0 = -1.0e30f, mr1 = -1.0e30f, lr0 = 0.f, lr1 = 0.f;
    float oacc[8][4];
#pragma unroll
    for (int n = 0; n < 8; n++)
#pragma unroll
        for (int c = 0; c < 4; c++) oacc[n][c] = 0.f;

    const int ntiles = 2 * qt + 2;
    uint4 kreg[2], vreg[2];

    auto gload = [&](int kt) {
        const size_t kb = ((size_t)(b * SEQ + kt * 64)) * DIM + h * HDIM;
        const size_t vb = ((size_t)(b * DIM + h * HDIM)) * SEQ + kt * 64;
#pragma unroll
        for (int v = 0; v < 2; v++) {
            int i = tid + v * 256;
            int r = i >> 3, cv = i & 7;
            kreg[v] = *(const uint4*)(Kp + kb + (size_t)r * DIM + cv * 8);
            vreg[v] = *(const uint4*)(Vh + vb + (size_t)r * SEQ + cv * 8);
        }
    };

    gload(0);

    for (int kt = 0; kt < ntiles; kt++) {
        __syncthreads();
#pragma unroll
        for (int v = 0; v < 2; v++) {
            int i = tid + v * 256;
            int r = i >> 3, cv = i & 7;
            *(uint4*)(Ks + r * STRH + cv * 8) = kreg[v];
            *(uint4*)(Vs + r * STRH + cv * 8) = vreg[v];
        }
        __syncthreads();

        if (kt + 1 < ntiles) gload(kt + 1);

        const int k0 = kt * 64;
        const bool active = (k0 <= q0 + w * 16 + 15);
        if (active) {
            // ---- S = Q K^T, bf16 m16n8k16 ----
            float sacc[8][4];
#pragma unroll
            for (int n = 0; n < 8; n++)
#pragma unroll
                for (int c = 0; c < 4; c++) sacc[n][c] = 0.f;

#pragma unroll
            for (int kc = 0; kc < 4; kc++) {
                uint32_t a[4];
                ldsm4(a, qsb + a_lane + kc * 32);
#pragma unroll
                for (int p = 0; p < 4; p++) {
                    uint32_t kr[4];
                    ldsm4(kr, ksb + b_lane + (uint32_t)(p * 16 * (STRH * 2)) + kc * 32);
                    mma16b(sacc[2 * p],     a, kr[0], kr[1]);
                    mma16b(sacc[2 * p + 1], a, kr[2], kr[3]);
                }
            }

            // ---- causal mask ----
            if (k0 + 63 > q0 + w * 16) {
                const int g0 = q0 + lrow0, g1 = q0 + lrow1;
#pragma unroll
                for (int n = 0; n < 8; n++) {
                    int cg = k0 + n * 8 + 2 * l4;
                    if (cg     > g0) sacc[n][0] = -1.0e30f;
                    if (cg + 1 > g0) sacc[n][1] = -1.0e30f;
                    if (cg     > g1) sacc[n][2] = -1.0e30f;
                    if (cg + 1 > g1) sacc[n][3] = -1.0e30f;
                }
            }

            // ---- online softmax (log2 domain) ----
            float mx0 = -1.0e30f, mx1 = -1.0e30f;
#pragma unroll
            for (int n = 0; n < 8; n++) {
                mx0 = fmaxf(mx0, fmaxf(sacc[n][0], sacc[n][1]));
                mx1 = fmaxf(mx1, fmaxf(sacc[n][2], sacc[n][3]));
            }
            mx0 = fmaxf(mx0, __shfl_xor_sync(0xffffffffu, mx0, 1));
            mx0 = fmaxf(mx0, __shfl_xor_sync(0xffffffffu, mx0, 2));
            mx1 = fmaxf(mx1, __shfl_xor_sync(0xffffffffu, mx1, 1));
            mx1 = fmaxf(mx1, __shfl_xor_sync(0xffffffffu, mx1, 2));

            float mn0 = fmaxf(mr0, mx0), mn1 = fmaxf(mr1, mx1);
            float al0 = ex2(mr0 - mn0),  al1 = ex2(mr1 - mn1);
            float s0 = 0.f, s1 = 0.f;
#pragma unroll
            for (int n = 0; n < 8; n++) {
                float p0 = ex2(sacc[n][0] - mn0);
                float p1 = ex2(sacc[n][1] - mn0);
                float p2 = ex2(sacc[n][2] - mn1);
                float p3 = ex2(sacc[n][3] - mn1);
                sacc[n][0] = p0; sacc[n][1] = p1; sacc[n][2] = p2; sacc[n][3] = p3;
                s0 += p0 + p1;
                s1 += p2 + p3;
            }
            s0 += __shfl_xor_sync(0xffffffffu, s0, 1);
            s0 += __shfl_xor_sync(0xffffffffu, s0, 2);
            s1 += __shfl_xor_sync(0xffffffffu, s1, 1);
            s1 += __shfl_xor_sync(0xffffffffu, s1, 2);
            lr0 = lr0 * al0 + s0;
            lr1 = lr1 * al1 + s1;
            mr0 = mn0; mr1 = mn1;

#pragma unroll
            for (int n = 0; n < 8; n++) {
                oacc[n][0] *= al0; oacc[n][1] *= al0;
                oacc[n][2] *= al1; oacc[n][3] *= al1;
            }

            // ---- write P as fp16x2 pairs, natural [q][kv] rows (warp-private) ----
#pragma unroll
            for (int n = 0; n < 8; n++) {
                int col = n * 8 + 2 * l4;
                *(uint32_t*)(Ps + lrow0 * STRH + col) = hf2(sacc[n][0], sacc[n][1]);
                *(uint32_t*)(Ps + lrow1 * STRH + col) = hf2(sacc[n][2], sacc[n][3]);
            }
            __syncwarp();

            // ---- O += P @ V, fp16 m16n8k16 (P a-frags, V b-frags via b16 ldsm) ----
#pragma unroll
            for (int kc = 0; kc < 4; kc++) {
                uint32_t a[4];
                ldsm4(a, psb + a_lane + kc * 32);
#pragma unroll
                for (int p = 0; p < 4; p++) {
                    uint32_t vr[4];
                    ldsm4(vr, vsb + b_lane + (uint32_t)(p * 16 * (STRH * 2)) + kc * 32);
                    mma16h(oacc[2 * p],     a, vr[0], vr[1]);
                    mma16h(oacc[2 * p + 1], a, vr[2], vr[3]);
                }
            }
            __syncwarp();
        }
    }

    const float inv0 = 1.f / lr0, inv1 = 1.f / lr1;
    const size_t ob0 = ((size_t)(b * SEQ + q0 + lrow0)) * DIM + h * HDIM;
    const size_t ob1 = ((size_t)(b * SEQ + q0 + lrow1)) * DIM + h * HDIM;
#pragma unroll
    for (int n = 0; n < 8; n++) {
        int col = n * 8 + 2 * l4;
        *(float2*)&Ctx[ob0 + col] = make_float2(__uint_as_float(f2t(oacc[n][0] * inv0)),
                                                __uint_as_float(f2t(oacc[n][1] * inv0)));
        *(float2*)&Ctx[ob1 + col] = make_float2(__uint_as_float(f2t(oacc[n][2] * inv1)),
                                                __uint_as_float(f2t(oacc[n][3] * inv1)));
    }
}

// ---------------- host launcher ----------------
extern "C" void kernel_launch(void* const* d_in, const int* in_sizes, int n_in,
                              void* d_out, int out_size)
{
    const float* x     = (const float*)d_in[0];
    // d_in[1] = mask (causal, hard-coded)
    const float* w_kvc = (const float*)d_in[2];
    const float* b_kvc = (const float*)d_in[3];
    const float* w_kvu = (const float*)d_in[4];
    const float* b_kvu = (const float*)d_in[5];
    const float* w_qc  = (const float*)d_in[6];
    const float* b_qc  = (const float*)d_in[7];
    const float* w_qu  = (const float*)d_in[8];
    const float* b_qu  = (const float*)d_in[9];
    const float* w_o   = (const float*)d_in[10];
    const float* b_o   = (const float*)d_in[11];
    float* out = (float*)d_out;

    float *lat, *qc, *ctx;
    uint16_t *kb, *qb, *vh;
    uint32_t *xt, *wkvc, *wqc, *wkvu, *wqu, *wo;
    cudaGetSymbolAddress((void**)&lat,  g_lat);
    cudaGetSymbolAddress((void**)&kb,   g_kb);
    cudaGetSymbolAddress((void**)&vh,   g_vh);
    cudaGetSymbolAddress((void**)&qc,   g_qc);
    cudaGetSymbolAddress((void**)&qb,   g_qb);
    cudaGetSymbolAddress((void**)&ctx,  g_ctx);
    cudaGetSymbolAddress((void**)&xt,   g_xt);
    cudaGetSymbolAddress((void**)&wkvc, g_wkvc);
    cudaGetSymbolAddress((void**)&wqc,  g_wqc);
    cudaGetSymbolAddress((void**)&wkvu, g_wkvu);
    cudaGetSymbolAddress((void**)&wqu,  g_wqu);
    cudaGetSymbolAddress((void**)&wo,   g_wo);

    cudaFuncSetAttribute(gemm_tt_kernel<0>, cudaFuncAttributeMaxDynamicSharedMemorySize, GEMM_SMEM);
    cudaFuncSetAttribute(fused_latqc_kernel, cudaFuncAttributeMaxDynamicSharedMemorySize, GEMM_SMEM);
    cudaFuncSetAttribute(fused_kvq_kernel, cudaFuncAttributeMaxDynamicSharedMemorySize, GEMM_SMEM);
    cudaFuncSetAttribute(flash_kernel, cudaFuncAttributeMaxDynamicSharedMemorySize, FL_SMEM);

    const int t0 = (DIM / 32) * (LATENT / 32);
    const int t1 = (DIM / 32) * (QRANK / 32);
    const int t2 = (LATENT / 32) * (2 * DIM / 32);
    const int t3 = (QRANK / 32) * (DIM / 32);
    const int t4 = (DIM / 32) * (DIM / 32);
    cvt_wT_kernel<<<t0 + t1 + t2 + t3 + t4, 256>>>(
        w_kvc, wkvc, DIM, LATENT, t0,
        w_qc,  wqc,  DIM, QRANK,  t1,
        w_kvu, wkvu, LATENT, 2 * DIM, t2,
        w_qu,  wqu,  QRANK, DIM, t3,
        w_o,   wo,   DIM, DIM);
    cvt_x_kernel<<<(T_TOK * DIM / 4 + 255) / 256, 256>>>((const float4*)x, (uint4*)xt, T_TOK * DIM / 4);

    // fused kv_latent + q_c  (tf32 out)
    fused_latqc_kernel<<<dim3(6, T_TOK / 128), 256, GEMM_SMEM>>>(
        xt, wkvc, b_kvc, lat, wqc, b_qc, qc);
    // fused kv_up (K bf16 + V fp16-T) + q_up (Q bf16, pre-scaled)
    fused_kvq_kernel<<<dim3(48, T_TOK / 128), 256, GEMM_SMEM>>>(
        (const uint32_t*)lat, wkvu, b_kvu, (float*)kb,
        (const uint32_t*)qc, wqu, b_qu, (float*)qb);
    // causal flash attention -> ctx (tf32-out)
    flash_kernel<<<dim3(SEQ / BQ, NHEADS, NBATCH), 256, FL_SMEM>>>(
        qb, kb, vh, ctx);
    // out = ctx @ w_o + b  (fp32 out)
    gemm_tt_kernel<0><<<dim3(DIM / 64, T_TOK / 128), 256, GEMM_SMEM>>>(
        (const uint32_t*)ctx, wo, b_o, out, DIM, DIM, 1.f);
}